// round 2
// baseline (speedup 1.0000x reference)
#include <cuda_runtime.h>
#include <math.h>

// ---------------- problem constants ----------------
#define NB   8
#define NC   256
#define NHW  16384     // 128*128
#define NTOK 131072    // NB*NHW
#define NHEAD 8
#define HDIM  32

// ---------------- scratch (device globals; no allocation allowed) ----------------
__device__ float g_cat [(size_t)NB * 768 * NHW];   // [B,3C,HW]
__device__ float g_xm  [(size_t)NB * NC  * NHW];   // x_multi [B,C,HW]
__device__ float g_tok [(size_t)NTOK * NC];        // LN'd tokens, row-major
__device__ float g_qkv [(size_t)NTOK * 768];
__device__ float g_att [(size_t)NTOK * NC];
__device__ float g_proj[(size_t)NTOK * NC];
__device__ float g_h1  [(size_t)NTOK * 1024];
__device__ float g_mean[NTOK];
__device__ float g_rstd[NTOK];

// ---------------- helpers ----------------
__device__ __forceinline__ float gelu_exact(float x) {
    return 0.5f * x * (1.0f + erff(x * 0.70710678118654752f));
}

// Forward (partition) mapping: token id -> global offset b*CHW + h*W + w.
// mode 0=window, 1=grid, 2=flat
__device__ __forceinline__ int pix_gather(int mode, int t) {
    int b = t >> 14;
    int r = t & 16383;
    int p;
    if (mode == 2) {
        p = r;
    } else {
        int win = r >> 6, pos = r & 63;
        int wy = win >> 4, wx = win & 15;   // window: (h/8, w/8); grid: (K1, K2)
        int py = pos >> 3, px = pos & 7;    // window: (py, px);  grid: (S1, S2)
        int h, w;
        if (mode == 0) { h = wy * 8 + py;  w = wx * 8 + px; }
        else           { h = py * 16 + wy; w = px * 16 + wx; }
        p = h * 128 + w;
    }
    return b * (NC * NHW) + p;
}

// Reverse (scatter) mapping. Window & flat are clean inverses of the forward
// mapping. Grid reverse in the reference uses transpose (0,5,2,1,3,4) with a
// flat reshape, which places token (K1,K2,S1,S2) at:
//   h = K2*8 + (K1>>1),  w = (K1&1)*64 + S1*8 + S2
__device__ __forceinline__ int pix_scatter(int mode, int t) {
    int b = t >> 14;
    int r = t & 16383;
    int p;
    if (mode == 2) {
        p = r;
    } else if (mode == 0) {
        int win = r >> 6, pos = r & 63;
        int wy = win >> 4, wx = win & 15;
        int py = pos >> 3, px = pos & 7;
        p = (wy * 8 + py) * 128 + (wx * 8 + px);
    } else {
        int win = r >> 6, pos = r & 63;
        int K1 = win >> 4, K2 = win & 15;
        int S1 = pos >> 3, S2 = pos & 7;
        int h = K2 * 8 + (K1 >> 1);
        int w = (K1 & 1) * 64 + S1 * 8 + S2;
        p = h * 128 + w;
    }
    return b * (NC * NHW) + p;
}

// ---------------- 1) fused depthwise convs (3x3,5x5,7x7) ----------------
// grid (16 tiles, C, B), block 256. 32x32 output tile, halo 3.
__global__ void dwconv3_kernel(const float* __restrict__ X,
                               const float* __restrict__ w1, const float* __restrict__ b1,
                               const float* __restrict__ w2, const float* __restrict__ b2,
                               const float* __restrict__ w3, const float* __restrict__ b3) {
    __shared__ float sx[38][39];
    __shared__ float swt[83];
    int c = blockIdx.y, b = blockIdx.z;
    int tile = blockIdx.x;
    int ty0 = (tile >> 2) * 32, tx0 = (tile & 3) * 32;
    const float* Xp = X + ((size_t)b * NC + c) * NHW;
    int tid = threadIdx.x;

    if (tid < 9)       swt[tid] = w1[c * 9 + tid];
    else if (tid < 34) swt[tid] = w2[c * 25 + (tid - 9)];
    else if (tid < 83) swt[tid] = w3[c * 49 + (tid - 34)];

    for (int i = tid; i < 38 * 38; i += 256) {
        int iy = i / 38, ix = i - iy * 38;
        int gy = ty0 + iy - 3, gx = tx0 + ix - 3;
        float v = 0.0f;
        if (gy >= 0 && gy < 128 && gx >= 0 && gx < 128) v = Xp[gy * 128 + gx];
        sx[iy][ix] = v;
    }
    __syncthreads();

    float bb1 = b1[c], bb2 = b2[c], bb3 = b3[c];
    size_t ob1 = ((size_t)b * 768 + c) * NHW;
    size_t ob2 = ((size_t)b * 768 + 256 + c) * NHW;
    size_t ob3 = ((size_t)b * 768 + 512 + c) * NHW;

    #pragma unroll
    for (int sub = 0; sub < 4; sub++) {
        int oy = (tid >> 5) + sub * 8;   // 0..31
        int ox = (tid & 31);             // 0..31
        int cy = oy + 3, cx = ox + 3;
        float a1 = bb1, a2 = bb2, a3 = bb3;
        #pragma unroll
        for (int dy = -3; dy <= 3; dy++) {
            #pragma unroll
            for (int dx = -3; dx <= 3; dx++) {
                float v = sx[cy + dy][cx + dx];
                a3 += v * swt[34 + (dy + 3) * 7 + (dx + 3)];
                if (dy >= -2 && dy <= 2 && dx >= -2 && dx <= 2)
                    a2 += v * swt[9 + (dy + 2) * 5 + (dx + 2)];
                if (dy >= -1 && dy <= 1 && dx >= -1 && dx <= 1)
                    a1 += v * swt[(dy + 1) * 3 + (dx + 1)];
            }
        }
        int po = (ty0 + oy) * 128 + tx0 + ox;
        g_cat[ob1 + po] = a1;
        g_cat[ob2 + po] = a2;
        g_cat[ob3 + po] = a3;
    }
}

// ---------------- 2) fuse GEMM: C[c,p] = sum_k wf[c,k]*cat[k,p] + bf[c] ----------------
__global__ void gemm_nn_fuse(const float* __restrict__ A, const float* __restrict__ Bc,
                             const float* __restrict__ biasM, float* __restrict__ Cc2) {
    __shared__ float As[16][64];
    __shared__ float Bs[16][64];
    int b = blockIdx.z;
    const float* Bm = Bc + (size_t)b * 768 * NHW;
    float* Cm = Cc2 + (size_t)b * NC * NHW;
    int tid = threadIdx.x;
    int m0 = blockIdx.y * 64, n0 = blockIdx.x * 64;
    int lrA = tid >> 2, lcA = tid & 3;
    int lrB = tid >> 4, lcB = tid & 15;
    int tm = (tid >> 4) * 4, tn = (tid & 15) * 4;
    float acc[4][4] = {};
    for (int k0 = 0; k0 < 768; k0 += 16) {
        float4 a = *(const float4*)&A[(size_t)(m0 + lrA) * 768 + k0 + lcA * 4];
        As[lcA * 4 + 0][lrA] = a.x; As[lcA * 4 + 1][lrA] = a.y;
        As[lcA * 4 + 2][lrA] = a.z; As[lcA * 4 + 3][lrA] = a.w;
        float4 bv = *(const float4*)&Bm[(size_t)(k0 + lrB) * NHW + n0 + lcB * 4];
        *(float4*)&Bs[lrB][lcB * 4] = bv;
        __syncthreads();
        #pragma unroll
        for (int kk = 0; kk < 16; kk++) {
            float4 ra = *(const float4*)&As[kk][tm];
            float4 rb = *(const float4*)&Bs[kk][tn];
            acc[0][0] += ra.x * rb.x; acc[0][1] += ra.x * rb.y; acc[0][2] += ra.x * rb.z; acc[0][3] += ra.x * rb.w;
            acc[1][0] += ra.y * rb.x; acc[1][1] += ra.y * rb.y; acc[1][2] += ra.y * rb.z; acc[1][3] += ra.y * rb.w;
            acc[2][0] += ra.z * rb.x; acc[2][1] += ra.z * rb.y; acc[2][2] += ra.z * rb.z; acc[2][3] += ra.z * rb.w;
            acc[3][0] += ra.w * rb.x; acc[3][1] += ra.w * rb.y; acc[3][2] += ra.w * rb.z; acc[3][3] += ra.w * rb.w;
        }
        __syncthreads();
    }
    #pragma unroll
    for (int i = 0; i < 4; i++) {
        float bm = biasM[m0 + tm + i];
        float4 o;
        o.x = acc[i][0] + bm; o.y = acc[i][1] + bm; o.z = acc[i][2] + bm; o.w = acc[i][3] + bm;
        *(float4*)&Cm[(size_t)(m0 + tm + i) * NHW + n0 + tn] = o;
    }
}

// ---------------- NT GEMM: C[M,N] = A[M,K] * B[N,K]^T + bias[n] (opt GELU) ----------------
template<bool GELU>
__global__ void gemm_nt(const float* __restrict__ A, const float* __restrict__ Bw,
                        const float* __restrict__ bias, float* __restrict__ Cm,
                        int N, int K) {
    __shared__ float As[16][64];
    __shared__ float Bs[16][64];
    int tid = threadIdx.x;
    size_t m0 = (size_t)blockIdx.y * 64;
    int n0 = blockIdx.x * 64;
    int lr = tid >> 2, lc = tid & 3;
    int tm = (tid >> 4) * 4, tn = (tid & 15) * 4;
    float acc[4][4] = {};
    const float* Ap = A + (m0 + lr) * K + lc * 4;
    const float* Bp = Bw + (size_t)(n0 + lr) * K + lc * 4;
    for (int k0 = 0; k0 < K; k0 += 16) {
        float4 a = *(const float4*)(Ap + k0);
        float4 bb = *(const float4*)(Bp + k0);
        As[lc * 4 + 0][lr] = a.x;  As[lc * 4 + 1][lr] = a.y;
        As[lc * 4 + 2][lr] = a.z;  As[lc * 4 + 3][lr] = a.w;
        Bs[lc * 4 + 0][lr] = bb.x; Bs[lc * 4 + 1][lr] = bb.y;
        Bs[lc * 4 + 2][lr] = bb.z; Bs[lc * 4 + 3][lr] = bb.w;
        __syncthreads();
        #pragma unroll
        for (int kk = 0; kk < 16; kk++) {
            float4 ra = *(const float4*)&As[kk][tm];
            float4 rb = *(const float4*)&Bs[kk][tn];
            acc[0][0] += ra.x * rb.x; acc[0][1] += ra.x * rb.y; acc[0][2] += ra.x * rb.z; acc[0][3] += ra.x * rb.w;
            acc[1][0] += ra.y * rb.x; acc[1][1] += ra.y * rb.y; acc[1][2] += ra.y * rb.z; acc[1][3] += ra.y * rb.w;
            acc[2][0] += ra.z * rb.x; acc[2][1] += ra.z * rb.y; acc[2][2] += ra.z * rb.z; acc[2][3] += ra.z * rb.w;
            acc[3][0] += ra.w * rb.x; acc[3][1] += ra.w * rb.y; acc[3][2] += ra.w * rb.z; acc[3][3] += ra.w * rb.w;
        }
        __syncthreads();
    }
    float b0 = bias[n0 + tn + 0], b1 = bias[n0 + tn + 1];
    float b2 = bias[n0 + tn + 2], b3 = bias[n0 + tn + 3];
    #pragma unroll
    for (int i = 0; i < 4; i++) {
        float4 o;
        o.x = acc[i][0] + b0; o.y = acc[i][1] + b1; o.z = acc[i][2] + b2; o.w = acc[i][3] + b3;
        if (GELU) { o.x = gelu_exact(o.x); o.y = gelu_exact(o.y); o.z = gelu_exact(o.z); o.w = gelu_exact(o.w); }
        *(float4*)&Cm[(m0 + tm + i) * N + n0 + tn] = o;
    }
}

// ---------------- LN stats: per pixel over channels ----------------
__global__ void ln_stats(const float* __restrict__ X) {
    int idx = blockIdx.x * 256 + threadIdx.x;        // 0..131071
    int b = idx >> 14, p = idx & 16383;
    const float* base = X + (size_t)b * NC * NHW + p;
    float s = 0.0f, s2 = 0.0f;
    #pragma unroll 8
    for (int c = 0; c < NC; c++) {
        float v = base[(size_t)c * NHW];
        s += v; s2 += v * v;
    }
    float m = s * (1.0f / NC);
    float var = s2 * (1.0f / NC) - m * m;
    g_mean[idx] = m;
    g_rstd[idx] = rsqrtf(var + 1e-5f);
}

// ---------------- gather + LN normalize -> token-major ----------------
__global__ void gather_ln(const float* __restrict__ X, const float* __restrict__ gamma,
                          const float* __restrict__ beta, float* __restrict__ T, int mode) {
    __shared__ float st[32 * 65];
    __shared__ float sm[64], sr[64];
    __shared__ int   spix[64];
    int tid = threadIdx.x;
    int t0 = blockIdx.x * 64;
    if (tid < 64) {
        int off = pix_gather(mode, t0 + tid);
        spix[tid] = off;
        int b = (t0 + tid) >> 14;
        int gi = b * NHW + (off - b * (NC * NHW));
        sm[tid] = g_mean[gi];
        sr[tid] = g_rstd[gi];
    }
    __syncthreads();
    for (int c0 = 0; c0 < NC; c0 += 32) {
        int cl = tid >> 3;
        int pbase = (tid & 7) * 8;
        size_t coff = (size_t)(c0 + cl) * NHW;
        #pragma unroll
        for (int i = 0; i < 8; i++) {
            int p = pbase + i;
            st[cl * 65 + p] = X[(size_t)spix[p] + coff];
        }
        __syncthreads();
        int p = tid >> 2, q = tid & 3;
        float m = sm[p], rs = sr[p];
        int cb = c0 + q * 8;
        float4 o0, o1;
        o0.x = (st[(q * 8 + 0) * 65 + p] - m) * rs * gamma[cb + 0] + beta[cb + 0];
        o0.y = (st[(q * 8 + 1) * 65 + p] - m) * rs * gamma[cb + 1] + beta[cb + 1];
        o0.z = (st[(q * 8 + 2) * 65 + p] - m) * rs * gamma[cb + 2] + beta[cb + 2];
        o0.w = (st[(q * 8 + 3) * 65 + p] - m) * rs * gamma[cb + 3] + beta[cb + 3];
        o1.x = (st[(q * 8 + 4) * 65 + p] - m) * rs * gamma[cb + 4] + beta[cb + 4];
        o1.y = (st[(q * 8 + 5) * 65 + p] - m) * rs * gamma[cb + 5] + beta[cb + 5];
        o1.z = (st[(q * 8 + 6) * 65 + p] - m) * rs * gamma[cb + 6] + beta[cb + 6];
        o1.w = (st[(q * 8 + 7) * 65 + p] - m) * rs * gamma[cb + 7] + beta[cb + 7];
        float* dst = &T[(size_t)(t0 + p) * NC + cb];
        *(float4*)dst = o0;
        *(float4*)(dst + 4) = o1;
        __syncthreads();
    }
}

// ---------------- scatter residual: dst[b,c,pix] = base[b,c,pix] + P[t,c] ----------------
__global__ void scatter_add(const float* __restrict__ P, const float* __restrict__ base,
                            float* __restrict__ dst, int mode) {
    __shared__ float st[32 * 65];
    __shared__ int   spix[64];
    int tid = threadIdx.x;
    int t0 = blockIdx.x * 64;
    if (tid < 64) spix[tid] = pix_scatter(mode, t0 + tid);
    __syncthreads();
    for (int c0 = 0; c0 < NC; c0 += 32) {
        int p = tid >> 2, q = tid & 3;
        const float* src = &P[(size_t)(t0 + p) * NC + c0 + q * 8];
        float4 v0 = *(const float4*)src;
        float4 v1 = *(const float4*)(src + 4);
        st[(q * 8 + 0) * 65 + p] = v0.x; st[(q * 8 + 1) * 65 + p] = v0.y;
        st[(q * 8 + 2) * 65 + p] = v0.z; st[(q * 8 + 3) * 65 + p] = v0.w;
        st[(q * 8 + 4) * 65 + p] = v1.x; st[(q * 8 + 5) * 65 + p] = v1.y;
        st[(q * 8 + 6) * 65 + p] = v1.z; st[(q * 8 + 7) * 65 + p] = v1.w;
        __syncthreads();
        int cl = tid >> 3;
        int pbase = (tid & 7) * 8;
        size_t coff = (size_t)(c0 + cl) * NHW;
        #pragma unroll
        for (int i = 0; i < 8; i++) {
            int p2 = pbase + i;
            size_t a = (size_t)spix[p2] + coff;
            dst[a] = base[a] + st[cl * 65 + p2];
        }
        __syncthreads();
    }
}

// ---------------- per-(window,head) attention, L=64, D=32 ----------------
__global__ void attn_kernel(const float* __restrict__ QKV, float* __restrict__ O) {
    __shared__ float sq[64 * 32], sk[64 * 32], sv[64 * 32];
    __shared__ float ss[64 * 65];
    int wh = blockIdx.x;
    int win = wh >> 3, head = wh & 7;
    int tid = threadIdx.x;
    const float* base = QKV + (size_t)win * 64 * 768 + head * 32;

    for (int i = tid; i < 512; i += 128) {
        int row = i >> 3, f4 = (i & 7) * 4;
        size_t off = (size_t)row * 768 + f4;
        *(float4*)&sq[row * 32 + f4] = *(const float4*)&base[off];
        *(float4*)&sk[row * 32 + f4] = *(const float4*)&base[off + 256];
        *(float4*)&sv[row * 32 + f4] = *(const float4*)&base[off + 512];
    }
    __syncthreads();

    int qi = tid >> 1, j0 = (tid & 1) * 32;
    float qreg[32];
    #pragma unroll
    for (int d = 0; d < 32; d++) qreg[d] = sq[qi * 32 + d];
    const float scale = 0.17677669529663687f;  // 1/sqrt(32)
    for (int j = 0; j < 32; j++) {
        int kj = j0 + j;
        float acc = 0.0f;
        #pragma unroll
        for (int d = 0; d < 32; d++) acc += qreg[d] * sk[kj * 32 + d];
        ss[qi * 65 + kj] = acc * scale;
    }
    __syncthreads();

    if (tid < 64) {
        float mx = -1e30f;
        #pragma unroll 8
        for (int j = 0; j < 64; j++) mx = fmaxf(mx, ss[tid * 65 + j]);
        float sum = 0.0f;
        #pragma unroll 8
        for (int j = 0; j < 64; j++) {
            float e = __expf(ss[tid * 65 + j] - mx);
            ss[tid * 65 + j] = e;
            sum += e;
        }
        float inv = 1.0f / sum;
        #pragma unroll 8
        for (int j = 0; j < 64; j++) ss[tid * 65 + j] *= inv;
    }
    __syncthreads();

    int d0 = (tid & 1) * 16;
    float acc[16];
    #pragma unroll
    for (int d = 0; d < 16; d++) acc[d] = 0.0f;
    for (int j = 0; j < 64; j++) {
        float pv = ss[qi * 65 + j];
        #pragma unroll
        for (int d = 0; d < 16; d++) acc[d] += pv * sv[j * 32 + d0 + d];
    }
    float* op = &O[((size_t)win * 64 + qi) * NC + head * 32 + d0];
    #pragma unroll
    for (int d = 0; d < 16; d += 4)
        *(float4*)&op[d] = make_float4(acc[d], acc[d + 1], acc[d + 2], acc[d + 3]);
}

// ---------------- launch ----------------
extern "C" void kernel_launch(void* const* d_in, const int* in_sizes, int n_in,
                              void* d_out, int out_size) {
    const float* x      = (const float*)d_in[0];
    const float* w1     = (const float*)d_in[1];
    const float* b1     = (const float*)d_in[2];
    const float* w2     = (const float*)d_in[3];
    const float* b2     = (const float*)d_in[4];
    const float* w3     = (const float*)d_in[5];
    const float* b3     = (const float*)d_in[6];
    const float* wf     = (const float*)d_in[7];
    const float* bf     = (const float*)d_in[8];
    const float* gw     = (const float*)d_in[9];
    const float* bw     = (const float*)d_in[10];
    const float* wqkv_w = (const float*)d_in[11];
    const float* bqkv_w = (const float*)d_in[12];
    const float* wo_w   = (const float*)d_in[13];
    const float* bo_w   = (const float*)d_in[14];
    const float* gg     = (const float*)d_in[15];
    const float* bg     = (const float*)d_in[16];
    const float* wqkv_g = (const float*)d_in[17];
    const float* bqkv_g = (const float*)d_in[18];
    const float* wo_g   = (const float*)d_in[19];
    const float* bo_g   = (const float*)d_in[20];
    const float* gm     = (const float*)d_in[21];
    const float* bm     = (const float*)d_in[22];
    const float* m1w    = (const float*)d_in[23];
    const float* m1b    = (const float*)d_in[24];
    const float* m2w    = (const float*)d_in[25];
    const float* m2b    = (const float*)d_in[26];
    float* out = (float*)d_out;

    void *p_cat, *p_xm, *p_tok, *p_qkv, *p_att, *p_proj, *p_h1;
    cudaGetSymbolAddress(&p_cat, g_cat);
    cudaGetSymbolAddress(&p_xm, g_xm);
    cudaGetSymbolAddress(&p_tok, g_tok);
    cudaGetSymbolAddress(&p_qkv, g_qkv);
    cudaGetSymbolAddress(&p_att, g_att);
    cudaGetSymbolAddress(&p_proj, g_proj);
    cudaGetSymbolAddress(&p_h1, g_h1);
    float* cat = (float*)p_cat;  float* xm = (float*)p_xm;   float* tok = (float*)p_tok;
    float* qkv = (float*)p_qkv;  float* att = (float*)p_att; float* proj = (float*)p_proj;
    float* h1 = (float*)p_h1;

    // 1) depthwise convs -> cat
    dwconv3_kernel<<<dim3(16, NC, NB), 256>>>(x, w1, b1, w2, b2, w3, b3);
    // 2) 1x1 fuse -> x_multi
    gemm_nn_fuse<<<dim3(256, 4, NB), 256>>>(wf, cat, bf, xm);

    // ---- window branch ----
    ln_stats<<<512, 256>>>(xm);
    gather_ln<<<2048, 256>>>(xm, gw, bw, tok, 0);
    gemm_nt<false><<<dim3(12, 2048), 256>>>(tok, wqkv_w, bqkv_w, qkv, 768, 256);
    attn_kernel<<<16384, 128>>>(qkv, att);
    gemm_nt<false><<<dim3(4, 2048), 256>>>(att, wo_w, bo_w, proj, 256, 256);
    scatter_add<<<2048, 256>>>(proj, x, out, 0);

    // ---- grid branch ----
    ln_stats<<<512, 256>>>(out);
    gather_ln<<<2048, 256>>>(out, gg, bg, tok, 1);
    gemm_nt<false><<<dim3(12, 2048), 256>>>(tok, wqkv_g, bqkv_g, qkv, 768, 256);
    attn_kernel<<<16384, 128>>>(qkv, att);
    gemm_nt<false><<<dim3(4, 2048), 256>>>(att, wo_g, bo_g, proj, 256, 256);
    scatter_add<<<2048, 256>>>(proj, out, out, 1);

    // ---- MLP ----
    ln_stats<<<512, 256>>>(out);
    gather_ln<<<2048, 256>>>(out, gm, bm, tok, 2);
    gemm_nt<true ><<<dim3(16, 2048), 256>>>(tok, m1w, m1b, h1, 1024, 256);
    gemm_nt<false><<<dim3(4, 2048), 256>>>(h1, m2w, m2b, proj, 256, 1024);
    scatter_add<<<2048, 256>>>(proj, out, out, 2);
}

// round 3
// speedup vs baseline: 1.7490x; 1.7490x over previous
#include <cuda_runtime.h>
#include <math.h>
#include <stdint.h>

// ---------------- problem constants ----------------
#define NB   8
#define NC   256
#define NHW  16384     // 128*128
#define NTOK 131072    // NB*NHW
#define NHEAD 8
#define HDIM  32

// ---------------- scratch (device globals; no allocation allowed) ----------------
__device__ float g_cat [(size_t)NB * 768 * NHW];   // [B,3C,HW]
__device__ float g_xm  [(size_t)NB * NC  * NHW];   // x_multi [B,C,HW]
__device__ float g_tok [(size_t)NTOK * NC];        // LN'd tokens, row-major
__device__ float g_qkv [(size_t)NTOK * 768];
__device__ float g_att [(size_t)NTOK * NC];
__device__ float g_proj[(size_t)NTOK * NC];
__device__ float g_h1  [(size_t)NTOK * 1024];
__device__ float g_mean[NTOK];
__device__ float g_rstd[NTOK];

// ---------------- helpers ----------------
__device__ __forceinline__ float gelu_exact(float x) {
    return 0.5f * x * (1.0f + erff(x * 0.70710678118654752f));
}

__device__ __forceinline__ uint32_t f2tf(float x) {
    uint32_t r;
    asm("cvt.rna.tf32.f32 %0, %1;" : "=r"(r) : "f"(x));
    return r;
}

__device__ __forceinline__ void mma_tf32(float* d, const uint32_t* a, const uint32_t* b) {
    asm volatile(
        "mma.sync.aligned.m16n8k8.row.col.f32.tf32.tf32.f32 "
        "{%0,%1,%2,%3}, {%4,%5,%6,%7}, {%8,%9}, {%0,%1,%2,%3};"
        : "+f"(d[0]), "+f"(d[1]), "+f"(d[2]), "+f"(d[3])
        : "r"(a[0]), "r"(a[1]), "r"(a[2]), "r"(a[3]), "r"(b[0]), "r"(b[1]));
}

// Forward (partition) mapping: token id -> global offset b*CHW + h*W + w.
// mode 0=window, 1=grid, 2=flat
__device__ __forceinline__ int pix_gather(int mode, int t) {
    int b = t >> 14;
    int r = t & 16383;
    int p;
    if (mode == 2) {
        p = r;
    } else {
        int win = r >> 6, pos = r & 63;
        int wy = win >> 4, wx = win & 15;
        int py = pos >> 3, px = pos & 7;
        int h, w;
        if (mode == 0) { h = wy * 8 + py;  w = wx * 8 + px; }
        else           { h = py * 16 + wy; w = px * 16 + wx; }
        p = h * 128 + w;
    }
    return b * (NC * NHW) + p;
}

// Reverse (scatter) mapping. Grid reverse places token (K1,K2,S1,S2) at:
//   h = K2*8 + (K1>>1),  w = (K1&1)*64 + S1*8 + S2   (reference's flat reshape)
__device__ __forceinline__ int pix_scatter(int mode, int t) {
    int b = t >> 14;
    int r = t & 16383;
    int p;
    if (mode == 2) {
        p = r;
    } else if (mode == 0) {
        int win = r >> 6, pos = r & 63;
        int wy = win >> 4, wx = win & 15;
        int py = pos >> 3, px = pos & 7;
        p = (wy * 8 + py) * 128 + (wx * 8 + px);
    } else {
        int win = r >> 6, pos = r & 63;
        int K1 = win >> 4, K2 = win & 15;
        int S1 = pos >> 3, S2 = pos & 7;
        int h = K2 * 8 + (K1 >> 1);
        int w = (K1 & 1) * 64 + S1 * 8 + S2;
        p = h * 128 + w;
    }
    return b * (NC * NHW) + p;
}

// ---------------- 1) fused depthwise convs (3x3,5x5,7x7) ----------------
__global__ void dwconv3_kernel(const float* __restrict__ X,
                               const float* __restrict__ w1, const float* __restrict__ b1,
                               const float* __restrict__ w2, const float* __restrict__ b2,
                               const float* __restrict__ w3, const float* __restrict__ b3) {
    __shared__ float sx[38][39];
    __shared__ float swt[83];
    int c = blockIdx.y, b = blockIdx.z;
    int tile = blockIdx.x;
    int ty0 = (tile >> 2) * 32, tx0 = (tile & 3) * 32;
    const float* Xp = X + ((size_t)b * NC + c) * NHW;
    int tid = threadIdx.x;

    if (tid < 9)       swt[tid] = w1[c * 9 + tid];
    else if (tid < 34) swt[tid] = w2[c * 25 + (tid - 9)];
    else if (tid < 83) swt[tid] = w3[c * 49 + (tid - 34)];

    for (int i = tid; i < 38 * 38; i += 256) {
        int iy = i / 38, ix = i - iy * 38;
        int gy = ty0 + iy - 3, gx = tx0 + ix - 3;
        float v = 0.0f;
        if (gy >= 0 && gy < 128 && gx >= 0 && gx < 128) v = Xp[gy * 128 + gx];
        sx[iy][ix] = v;
    }
    __syncthreads();

    float bb1 = b1[c], bb2 = b2[c], bb3 = b3[c];
    size_t ob1 = ((size_t)b * 768 + c) * NHW;
    size_t ob2 = ((size_t)b * 768 + 256 + c) * NHW;
    size_t ob3 = ((size_t)b * 768 + 512 + c) * NHW;

    #pragma unroll
    for (int sub = 0; sub < 4; sub++) {
        int oy = (tid >> 5) + sub * 8;
        int ox = (tid & 31);
        int cy = oy + 3, cx = ox + 3;
        float a1 = bb1, a2 = bb2, a3 = bb3;
        #pragma unroll
        for (int dy = -3; dy <= 3; dy++) {
            #pragma unroll
            for (int dx = -3; dx <= 3; dx++) {
                float v = sx[cy + dy][cx + dx];
                a3 += v * swt[34 + (dy + 3) * 7 + (dx + 3)];
                if (dy >= -2 && dy <= 2 && dx >= -2 && dx <= 2)
                    a2 += v * swt[9 + (dy + 2) * 5 + (dx + 2)];
                if (dy >= -1 && dy <= 1 && dx >= -1 && dx <= 1)
                    a1 += v * swt[(dy + 1) * 3 + (dx + 1)];
            }
        }
        int po = (ty0 + oy) * 128 + tx0 + ox;
        g_cat[ob1 + po] = a1;
        g_cat[ob2 + po] = a2;
        g_cat[ob3 + po] = a3;
    }
}

// ================= TF32 tensor-core GEMMs =================
// Block tile 128(M) x 64(N), BK=32, 8 warps (4x2), warp tile 32x32.
// SMEM layout: row stride 40 floats; within a row, k-chunk c (8 cols) is stored
// at physical chunk (c ^ ((row>>2)&3)); within a chunk, pair (k, k+4) adjacent:
// offset = chunkphys*8 + 2*(k&3) + (k>>2 within chunk). Fragment LDS.64 are
// bank-conflict-free (starts 0/8/16/24 + 2q).

// ---- NT: C[M,N] = A[M,K] * B[N,K]^T + bias[n], optional exact GELU ----
template<bool GELU>
__global__ __launch_bounds__(256, 2) void gemm_tf32_nt(
        const float* __restrict__ A, const float* __restrict__ B,
        const float* __restrict__ bias, float* __restrict__ C, int N, int K) {
    __shared__ uint32_t As[128 * 40];
    __shared__ uint32_t Bs[64 * 40];
    const int tid = threadIdx.x;
    const int lane = tid & 31, warp = tid >> 5;
    const int wm = warp >> 1, wn = warp & 1;
    const int g = lane >> 2, q = lane & 3;
    const size_t m0 = (size_t)blockIdx.y * 128;
    const int n0 = blockIdx.x * 64;

    const int ar = tid >> 1;          // 0..127
    const int ach = (tid & 1) * 2;    // chunk base 0 or 2
    const int br = tid >> 2;          // 0..63
    const int bch = tid & 3;          // chunk 0..3
    const float* Ag = A + (m0 + ar) * K + ach * 8;
    const float* Bg = B + (size_t)(n0 + br) * K + bch * 8;
    const int asw = (ar >> 2) & 3;
    const int bsw = (br >> 2) & 3;
    uint32_t* Asr = As + ar * 40;
    uint32_t* Bsr = Bs + br * 40;

    float acc[2][4][4];
    #pragma unroll
    for (int i = 0; i < 2; i++)
        #pragma unroll
        for (int j = 0; j < 4; j++)
            #pragma unroll
            for (int k = 0; k < 4; k++) acc[i][j][k] = 0.0f;

    for (int k0 = 0; k0 < K; k0 += 32) {
        #pragma unroll
        for (int c = 0; c < 2; c++) {
            float4 lo = *(const float4*)(Ag + k0 + c * 8);
            float4 hi = *(const float4*)(Ag + k0 + c * 8 + 4);
            uint2* dst = (uint2*)(Asr + ((ach + c) ^ asw) * 8);
            dst[0] = make_uint2(f2tf(lo.x), f2tf(hi.x));
            dst[1] = make_uint2(f2tf(lo.y), f2tf(hi.y));
            dst[2] = make_uint2(f2tf(lo.z), f2tf(hi.z));
            dst[3] = make_uint2(f2tf(lo.w), f2tf(hi.w));
        }
        {
            float4 lo = *(const float4*)(Bg + k0);
            float4 hi = *(const float4*)(Bg + k0 + 4);
            uint2* dst = (uint2*)(Bsr + (bch ^ bsw) * 8);
            dst[0] = make_uint2(f2tf(lo.x), f2tf(hi.x));
            dst[1] = make_uint2(f2tf(lo.y), f2tf(hi.y));
            dst[2] = make_uint2(f2tf(lo.z), f2tf(hi.z));
            dst[3] = make_uint2(f2tf(lo.w), f2tf(hi.w));
        }
        __syncthreads();
        #pragma unroll
        for (int kc = 0; kc < 4; kc++) {
            uint32_t afr[2][4], bfr[4][2];
            #pragma unroll
            for (int mt = 0; mt < 2; mt++) {
                int r0 = wm * 32 + mt * 16 + g;
                int r1 = r0 + 8;
                uint2 lo = *(uint2*)&As[r0 * 40 + ((kc ^ ((r0 >> 2) & 3)) * 8) + 2 * q];
                uint2 hi = *(uint2*)&As[r1 * 40 + ((kc ^ ((r1 >> 2) & 3)) * 8) + 2 * q];
                afr[mt][0] = lo.x; afr[mt][1] = hi.x; afr[mt][2] = lo.y; afr[mt][3] = hi.y;
            }
            #pragma unroll
            for (int nt = 0; nt < 4; nt++) {
                int rn = wn * 32 + nt * 8 + g;
                uint2 bb = *(uint2*)&Bs[rn * 40 + ((kc ^ ((rn >> 2) & 3)) * 8) + 2 * q];
                bfr[nt][0] = bb.x; bfr[nt][1] = bb.y;
            }
            #pragma unroll
            for (int mt = 0; mt < 2; mt++)
                #pragma unroll
                for (int nt = 0; nt < 4; nt++)
                    mma_tf32(acc[mt][nt], afr[mt], bfr[nt]);
        }
        __syncthreads();
    }

    #pragma unroll
    for (int mt = 0; mt < 2; mt++) {
        size_t rg = m0 + wm * 32 + mt * 16 + g;
        #pragma unroll
        for (int nt = 0; nt < 4; nt++) {
            int cb = n0 + wn * 32 + nt * 8 + 2 * q;
            float b0 = bias[cb], b1 = bias[cb + 1];
            float v0 = acc[mt][nt][0] + b0, v1 = acc[mt][nt][1] + b1;
            float v2 = acc[mt][nt][2] + b0, v3 = acc[mt][nt][3] + b1;
            if (GELU) {
                v0 = gelu_exact(v0); v1 = gelu_exact(v1);
                v2 = gelu_exact(v2); v3 = gelu_exact(v3);
            }
            *(float2*)&C[rg * N + cb] = make_float2(v0, v1);
            *(float2*)&C[(rg + 8) * N + cb] = make_float2(v2, v3);
        }
    }
}

// ---- Fuse (NN): C[m,n] = sum_k A[m,k] * Bm[k,n] + bias[m]; per-batch ----
// A = wf [256,768]; Bm = cat [768, NHW]; C = x_multi [256, NHW]
__global__ __launch_bounds__(256, 2) void gemm_tf32_fuse(
        const float* __restrict__ A, const float* __restrict__ Ball,
        const float* __restrict__ biasRow, float* __restrict__ Call) {
    __shared__ uint32_t As[128 * 40];
    __shared__ uint32_t Bs[64 * 40];
    const int tid = threadIdx.x;
    const int lane = tid & 31, warp = tid >> 5;
    const int wm = warp >> 1, wn = warp & 1;
    const int g = lane >> 2, q = lane & 3;
    const int K = 768;
    const int m0 = blockIdx.y * 128;
    const int n0 = blockIdx.x * 64;
    const int b = blockIdx.z;
    const float* B = Ball + (size_t)b * 768 * NHW;
    float* C = Call + (size_t)b * NC * NHW;

    const int ar = tid >> 1;
    const int ach = (tid & 1) * 2;
    const float* Ag = A + (size_t)(m0 + ar) * K + ach * 8;
    const int asw = (ar >> 2) & 3;
    uint32_t* Asr = As + ar * 40;

    // B loader: transpose [k][n] -> Bs[n][k]
    const int fkk = tid >> 3;          // 0..31
    const int fnn = (tid & 7) * 8;     // 0..56
    const int fch = fkk >> 3;          // k-chunk
    const int fq  = fkk & 3;
    const int fh  = (fkk >> 2) & 1;    // pair half
    const float* Bgf = B + (size_t)fkk * NHW + n0 + fnn;

    float acc[2][4][4];
    #pragma unroll
    for (int i = 0; i < 2; i++)
        #pragma unroll
        for (int j = 0; j < 4; j++)
            #pragma unroll
            for (int k = 0; k < 4; k++) acc[i][j][k] = 0.0f;

    for (int k0 = 0; k0 < K; k0 += 32) {
        #pragma unroll
        for (int c = 0; c < 2; c++) {
            float4 lo = *(const float4*)(Ag + k0 + c * 8);
            float4 hi = *(const float4*)(Ag + k0 + c * 8 + 4);
            uint2* dst = (uint2*)(Asr + ((ach + c) ^ asw) * 8);
            dst[0] = make_uint2(f2tf(lo.x), f2tf(hi.x));
            dst[1] = make_uint2(f2tf(lo.y), f2tf(hi.y));
            dst[2] = make_uint2(f2tf(lo.z), f2tf(hi.z));
            dst[3] = make_uint2(f2tf(lo.w), f2tf(hi.w));
        }
        {
            float4 v0 = *(const float4*)(Bgf + (size_t)k0 * NHW);
            float4 v1 = *(const float4*)(Bgf + (size_t)k0 * NHW + 4);
            float vv[8] = {v0.x, v0.y, v0.z, v0.w, v1.x, v1.y, v1.z, v1.w};
            #pragma unroll
            for (int j = 0; j < 8; j++) {
                int n = fnn + j;
                Bs[n * 40 + ((fch ^ ((n >> 2) & 3)) * 8) + 2 * fq + fh] = f2tf(vv[j]);
            }
        }
        __syncthreads();
        #pragma unroll
        for (int kc = 0; kc < 4; kc++) {
            uint32_t afr[2][4], bfr[4][2];
            #pragma unroll
            for (int mt = 0; mt < 2; mt++) {
                int r0 = wm * 32 + mt * 16 + g;
                int r1 = r0 + 8;
                uint2 lo = *(uint2*)&As[r0 * 40 + ((kc ^ ((r0 >> 2) & 3)) * 8) + 2 * q];
                uint2 hi = *(uint2*)&As[r1 * 40 + ((kc ^ ((r1 >> 2) & 3)) * 8) + 2 * q];
                afr[mt][0] = lo.x; afr[mt][1] = hi.x; afr[mt][2] = lo.y; afr[mt][3] = hi.y;
            }
            #pragma unroll
            for (int nt = 0; nt < 4; nt++) {
                int rn = wn * 32 + nt * 8 + g;
                uint2 bb = *(uint2*)&Bs[rn * 40 + ((kc ^ ((rn >> 2) & 3)) * 8) + 2 * q];
                bfr[nt][0] = bb.x; bfr[nt][1] = bb.y;
            }
            #pragma unroll
            for (int mt = 0; mt < 2; mt++)
                #pragma unroll
                for (int nt = 0; nt < 4; nt++)
                    mma_tf32(acc[mt][nt], afr[mt], bfr[nt]);
        }
        __syncthreads();
    }

    #pragma unroll
    for (int mt = 0; mt < 2; mt++) {
        int rg = m0 + wm * 32 + mt * 16 + g;
        float br0 = biasRow[rg], br8 = biasRow[rg + 8];
        #pragma unroll
        for (int nt = 0; nt < 4; nt++) {
            int cb = n0 + wn * 32 + nt * 8 + 2 * q;
            *(float2*)&C[(size_t)rg * NHW + cb] =
                make_float2(acc[mt][nt][0] + br0, acc[mt][nt][1] + br0);
            *(float2*)&C[(size_t)(rg + 8) * NHW + cb] =
                make_float2(acc[mt][nt][2] + br8, acc[mt][nt][3] + br8);
        }
    }
}

// ---------------- LN stats: per pixel over channels ----------------
__global__ void ln_stats(const float* __restrict__ X) {
    int idx = blockIdx.x * 256 + threadIdx.x;
    int b = idx >> 14, p = idx & 16383;
    const float* base = X + (size_t)b * NC * NHW + p;
    float s = 0.0f, s2 = 0.0f;
    #pragma unroll 8
    for (int c = 0; c < NC; c++) {
        float v = base[(size_t)c * NHW];
        s += v; s2 += v * v;
    }
    float m = s * (1.0f / NC);
    float var = s2 * (1.0f / NC) - m * m;
    g_mean[idx] = m;
    g_rstd[idx] = rsqrtf(var + 1e-5f);
}

// ---------------- gather + LN normalize -> token-major ----------------
__global__ void gather_ln(const float* __restrict__ X, const float* __restrict__ gamma,
                          const float* __restrict__ beta, float* __restrict__ T, int mode) {
    __shared__ float st[32 * 65];
    __shared__ float sm[64], sr[64];
    __shared__ int   spix[64];
    int tid = threadIdx.x;
    int t0 = blockIdx.x * 64;
    if (tid < 64) {
        int off = pix_gather(mode, t0 + tid);
        spix[tid] = off;
        int b = (t0 + tid) >> 14;
        int gi = b * NHW + (off - b * (NC * NHW));
        sm[tid] = g_mean[gi];
        sr[tid] = g_rstd[gi];
    }
    __syncthreads();
    for (int c0 = 0; c0 < NC; c0 += 32) {
        int cl = tid >> 3;
        int pbase = (tid & 7) * 8;
        size_t coff = (size_t)(c0 + cl) * NHW;
        #pragma unroll
        for (int i = 0; i < 8; i++) {
            int p = pbase + i;
            st[cl * 65 + p] = X[(size_t)spix[p] + coff];
        }
        __syncthreads();
        int p = tid >> 2, q = tid & 3;
        float m = sm[p], rs = sr[p];
        int cb = c0 + q * 8;
        float4 o0, o1;
        o0.x = (st[(q * 8 + 0) * 65 + p] - m) * rs * gamma[cb + 0] + beta[cb + 0];
        o0.y = (st[(q * 8 + 1) * 65 + p] - m) * rs * gamma[cb + 1] + beta[cb + 1];
        o0.z = (st[(q * 8 + 2) * 65 + p] - m) * rs * gamma[cb + 2] + beta[cb + 2];
        o0.w = (st[(q * 8 + 3) * 65 + p] - m) * rs * gamma[cb + 3] + beta[cb + 3];
        o1.x = (st[(q * 8 + 4) * 65 + p] - m) * rs * gamma[cb + 4] + beta[cb + 4];
        o1.y = (st[(q * 8 + 5) * 65 + p] - m) * rs * gamma[cb + 5] + beta[cb + 5];
        o1.z = (st[(q * 8 + 6) * 65 + p] - m) * rs * gamma[cb + 6] + beta[cb + 6];
        o1.w = (st[(q * 8 + 7) * 65 + p] - m) * rs * gamma[cb + 7] + beta[cb + 7];
        float* dst = &T[(size_t)(t0 + p) * NC + cb];
        *(float4*)dst = o0;
        *(float4*)(dst + 4) = o1;
        __syncthreads();
    }
}

// ---------------- scatter residual: dst[b,c,pix] = base[b,c,pix] + P[t,c] ----------------
__global__ void scatter_add(const float* __restrict__ P, const float* __restrict__ base,
                            float* __restrict__ dst, int mode) {
    __shared__ float st[32 * 65];
    __shared__ int   spix[64];
    int tid = threadIdx.x;
    int t0 = blockIdx.x * 64;
    if (tid < 64) spix[tid] = pix_scatter(mode, t0 + tid);
    __syncthreads();
    for (int c0 = 0; c0 < NC; c0 += 32) {
        int p = tid >> 2, q = tid & 3;
        const float* src = &P[(size_t)(t0 + p) * NC + c0 + q * 8];
        float4 v0 = *(const float4*)src;
        float4 v1 = *(const float4*)(src + 4);
        st[(q * 8 + 0) * 65 + p] = v0.x; st[(q * 8 + 1) * 65 + p] = v0.y;
        st[(q * 8 + 2) * 65 + p] = v0.z; st[(q * 8 + 3) * 65 + p] = v0.w;
        st[(q * 8 + 4) * 65 + p] = v1.x; st[(q * 8 + 5) * 65 + p] = v1.y;
        st[(q * 8 + 6) * 65 + p] = v1.z; st[(q * 8 + 7) * 65 + p] = v1.w;
        __syncthreads();
        int cl = tid >> 3;
        int pbase = (tid & 7) * 8;
        size_t coff = (size_t)(c0 + cl) * NHW;
        #pragma unroll
        for (int i = 0; i < 8; i++) {
            int p2 = pbase + i;
            size_t a = (size_t)spix[p2] + coff;
            dst[a] = base[a] + st[cl * 65 + p2];
        }
        __syncthreads();
    }
}

// ---------------- per-(window,head) attention, L=64, D=32 ----------------
__global__ void attn_kernel(const float* __restrict__ QKV, float* __restrict__ O) {
    __shared__ float sq[64 * 32], sk[64 * 32], sv[64 * 32];
    __shared__ float ss[64 * 65];
    int wh = blockIdx.x;
    int win = wh >> 3, head = wh & 7;
    int tid = threadIdx.x;
    const float* base = QKV + (size_t)win * 64 * 768 + head * 32;

    for (int i = tid; i < 512; i += 128) {
        int row = i >> 3, f4 = (i & 7) * 4;
        size_t off = (size_t)row * 768 + f4;
        *(float4*)&sq[row * 32 + f4] = *(const float4*)&base[off];
        *(float4*)&sk[row * 32 + f4] = *(const float4*)&base[off + 256];
        *(float4*)&sv[row * 32 + f4] = *(const float4*)&base[off + 512];
    }
    __syncthreads();

    int qi = tid >> 1, j0 = (tid & 1) * 32;
    float qreg[32];
    #pragma unroll
    for (int d = 0; d < 32; d++) qreg[d] = sq[qi * 32 + d];
    const float scale = 0.17677669529663687f;
    for (int j = 0; j < 32; j++) {
        int kj = j0 + j;
        float acc = 0.0f;
        #pragma unroll
        for (int d = 0; d < 32; d++) acc += qreg[d] * sk[kj * 32 + d];
        ss[qi * 65 + kj] = acc * scale;
    }
    __syncthreads();

    if (tid < 64) {
        float mx = -1e30f;
        #pragma unroll 8
        for (int j = 0; j < 64; j++) mx = fmaxf(mx, ss[tid * 65 + j]);
        float sum = 0.0f;
        #pragma unroll 8
        for (int j = 0; j < 64; j++) {
            float e = __expf(ss[tid * 65 + j] - mx);
            ss[tid * 65 + j] = e;
            sum += e;
        }
        float inv = 1.0f / sum;
        #pragma unroll 8
        for (int j = 0; j < 64; j++) ss[tid * 65 + j] *= inv;
    }
    __syncthreads();

    int d0 = (tid & 1) * 16;
    float acc[16];
    #pragma unroll
    for (int d = 0; d < 16; d++) acc[d] = 0.0f;
    for (int j = 0; j < 64; j++) {
        float pv = ss[qi * 65 + j];
        #pragma unroll
        for (int d = 0; d < 16; d++) acc[d] += pv * sv[j * 32 + d0 + d];
    }
    float* op = &O[((size_t)win * 64 + qi) * NC + head * 32 + d0];
    #pragma unroll
    for (int d = 0; d < 16; d += 4)
        *(float4*)&op[d] = make_float4(acc[d], acc[d + 1], acc[d + 2], acc[d + 3]);
}

// ---------------- launch ----------------
extern "C" void kernel_launch(void* const* d_in, const int* in_sizes, int n_in,
                              void* d_out, int out_size) {
    const float* x      = (const float*)d_in[0];
    const float* w1     = (const float*)d_in[1];
    const float* b1     = (const float*)d_in[2];
    const float* w2     = (const float*)d_in[3];
    const float* b2     = (const float*)d_in[4];
    const float* w3     = (const float*)d_in[5];
    const float* b3     = (const float*)d_in[6];
    const float* wf     = (const float*)d_in[7];
    const float* bf     = (const float*)d_in[8];
    const float* gw     = (const float*)d_in[9];
    const float* bw     = (const float*)d_in[10];
    const float* wqkv_w = (const float*)d_in[11];
    const float* bqkv_w = (const float*)d_in[12];
    const float* wo_w   = (const float*)d_in[13];
    const float* bo_w   = (const float*)d_in[14];
    const float* gg     = (const float*)d_in[15];
    const float* bg     = (const float*)d_in[16];
    const float* wqkv_g = (const float*)d_in[17];
    const float* bqkv_g = (const float*)d_in[18];
    const float* wo_g   = (const float*)d_in[19];
    const float* bo_g   = (const float*)d_in[20];
    const float* gm     = (const float*)d_in[21];
    const float* bm     = (const float*)d_in[22];
    const float* m1w    = (const float*)d_in[23];
    const float* m1b    = (const float*)d_in[24];
    const float* m2w    = (const float*)d_in[25];
    const float* m2b    = (const float*)d_in[26];
    float* out = (float*)d_out;

    void *p_cat, *p_xm, *p_tok, *p_qkv, *p_att, *p_proj, *p_h1;
    cudaGetSymbolAddress(&p_cat, g_cat);
    cudaGetSymbolAddress(&p_xm, g_xm);
    cudaGetSymbolAddress(&p_tok, g_tok);
    cudaGetSymbolAddress(&p_qkv, g_qkv);
    cudaGetSymbolAddress(&p_att, g_att);
    cudaGetSymbolAddress(&p_proj, g_proj);
    cudaGetSymbolAddress(&p_h1, g_h1);
    float* cat = (float*)p_cat;  float* xm = (float*)p_xm;   float* tok = (float*)p_tok;
    float* qkv = (float*)p_qkv;  float* att = (float*)p_att; float* proj = (float*)p_proj;
    float* h1 = (float*)p_h1;

    // 1) depthwise convs -> cat
    dwconv3_kernel<<<dim3(16, NC, NB), 256>>>(x, w1, b1, w2, b2, w3, b3);
    // 2) 1x1 fuse -> x_multi (tf32 tensor cores)
    gemm_tf32_fuse<<<dim3(256, 2, NB), 256>>>(wf, cat, bf, xm);

    // ---- window branch ----
    ln_stats<<<512, 256>>>(xm);
    gather_ln<<<2048, 256>>>(xm, gw, bw, tok, 0);
    gemm_tf32_nt<false><<<dim3(12, 1024), 256>>>(tok, wqkv_w, bqkv_w, qkv, 768, 256);
    attn_kernel<<<16384, 128>>>(qkv, att);
    gemm_tf32_nt<false><<<dim3(4, 1024), 256>>>(att, wo_w, bo_w, proj, 256, 256);
    scatter_add<<<2048, 256>>>(proj, x, out, 0);

    // ---- grid branch ----
    ln_stats<<<512, 256>>>(out);
    gather_ln<<<2048, 256>>>(out, gg, bg, tok, 1);
    gemm_tf32_nt<false><<<dim3(12, 1024), 256>>>(tok, wqkv_g, bqkv_g, qkv, 768, 256);
    attn_kernel<<<16384, 128>>>(qkv, att);
    gemm_tf32_nt<false><<<dim3(4, 1024), 256>>>(att, wo_g, bo_g, proj, 256, 256);
    scatter_add<<<2048, 256>>>(proj, out, out, 1);

    // ---- MLP ----
    ln_stats<<<512, 256>>>(out);
    gather_ln<<<2048, 256>>>(out, gm, bm, tok, 2);
    gemm_tf32_nt<true ><<<dim3(16, 1024), 256>>>(tok, m1w, m1b, h1, 1024, 256);
    gemm_tf32_nt<false><<<dim3(4, 1024), 256>>>(h1, m2w, m2b, proj, 256, 1024);
    scatter_add<<<2048, 256>>>(proj, out, out, 2);
}

// round 4
// speedup vs baseline: 2.0579x; 1.1766x over previous
#include <cuda_runtime.h>
#include <math.h>
#include <stdint.h>

// ---------------- problem constants ----------------
#define NB   8
#define NC   256
#define NHW  16384     // 128*128
#define NTOK 131072    // NB*NHW

// ---------------- scratch (device globals) ----------------
__device__ float g_cat [(size_t)NB * 768 * NHW];   // [B,3C,HW]
__device__ float g_xm  [(size_t)NTOK * NC];        // residual stream R[t][c] (token-major)
__device__ float g_xtok[(size_t)NTOK * NC];        // x transposed to token-major
__device__ float g_tok [(size_t)NTOK * NC];        // LN'd tokens
__device__ float g_qkv [(size_t)NTOK * 768];
__device__ float g_att [(size_t)NTOK * NC];
__device__ float g_proj[(size_t)NTOK * NC];
__device__ float g_h1  [(size_t)NTOK * 1024];

// ---------------- helpers ----------------
__device__ __forceinline__ float gelu_exact(float x) {
    return 0.5f * x * (1.0f + erff(x * 0.70710678118654752f));
}
__device__ __forceinline__ uint32_t f2tf(float x) {
    uint32_t r;
    asm("cvt.rna.tf32.f32 %0, %1;" : "=r"(r) : "f"(x));
    return r;
}
__device__ __forceinline__ void mma_tf32(float* d, const uint32_t* a, const uint32_t* b) {
    asm volatile(
        "mma.sync.aligned.m16n8k8.row.col.f32.tf32.tf32.f32 "
        "{%0,%1,%2,%3}, {%4,%5,%6,%7}, {%8,%9}, {%0,%1,%2,%3};"
        : "+f"(d[0]), "+f"(d[1]), "+f"(d[2]), "+f"(d[3])
        : "r"(a[0]), "r"(a[1]), "r"(a[2]), "r"(a[3]), "r"(b[0]), "r"(b[1]));
}

// ---------------- 1) fused depthwise convs (3x3,5x5,7x7) ----------------
__global__ void dwconv3_kernel(const float* __restrict__ X,
                               const float* __restrict__ w1, const float* __restrict__ b1,
                               const float* __restrict__ w2, const float* __restrict__ b2,
                               const float* __restrict__ w3, const float* __restrict__ b3) {
    __shared__ float sx[38][39];
    __shared__ float swt[83];
    int c = blockIdx.y, b = blockIdx.z;
    int tile = blockIdx.x;
    int ty0 = (tile >> 2) * 32, tx0 = (tile & 3) * 32;
    const float* Xp = X + ((size_t)b * NC + c) * NHW;
    int tid = threadIdx.x;

    if (tid < 9)       swt[tid] = w1[c * 9 + tid];
    else if (tid < 34) swt[tid] = w2[c * 25 + (tid - 9)];
    else if (tid < 83) swt[tid] = w3[c * 49 + (tid - 34)];

    for (int i = tid; i < 38 * 38; i += 256) {
        int iy = i / 38, ix = i - iy * 38;
        int gy = ty0 + iy - 3, gx = tx0 + ix - 3;
        float v = 0.0f;
        if (gy >= 0 && gy < 128 && gx >= 0 && gx < 128) v = Xp[gy * 128 + gx];
        sx[iy][ix] = v;
    }
    __syncthreads();

    float bb1 = b1[c], bb2 = b2[c], bb3 = b3[c];
    size_t ob1 = ((size_t)b * 768 + c) * NHW;
    size_t ob2 = ((size_t)b * 768 + 256 + c) * NHW;
    size_t ob3 = ((size_t)b * 768 + 512 + c) * NHW;

    #pragma unroll
    for (int sub = 0; sub < 4; sub++) {
        int oy = (tid >> 5) + sub * 8;
        int ox = (tid & 31);
        int cy = oy + 3, cx = ox + 3;
        float a1 = bb1, a2 = bb2, a3 = bb3;
        #pragma unroll
        for (int dy = -3; dy <= 3; dy++) {
            #pragma unroll
            for (int dx = -3; dx <= 3; dx++) {
                float v = sx[cy + dy][cx + dx];
                a3 += v * swt[34 + (dy + 3) * 7 + (dx + 3)];
                if (dy >= -2 && dy <= 2 && dx >= -2 && dx <= 2)
                    a2 += v * swt[9 + (dy + 2) * 5 + (dx + 2)];
                if (dy >= -1 && dy <= 1 && dx >= -1 && dx <= 1)
                    a1 += v * swt[(dy + 1) * 3 + (dx + 1)];
            }
        }
        int po = (ty0 + oy) * 128 + tx0 + ox;
        g_cat[ob1 + po] = a1;
        g_cat[ob2 + po] = a2;
        g_cat[ob3 + po] = a3;
    }
}

// ---------------- transpose x [B,C,HW] -> token-major [t][c] ----------------
__global__ void to_tok(const float* __restrict__ X, float* __restrict__ T) {
    __shared__ float sm[64][65];
    int p0 = blockIdx.x * 64, c0 = blockIdx.y * 64, b = blockIdx.z;
    int tid = threadIdx.x;
    #pragma unroll
    for (int it = 0; it < 4; it++) {
        int c = it * 16 + (tid >> 4);
        int p4 = (tid & 15) * 4;
        float4 v = *(const float4*)&X[((size_t)(b * NC + c0 + c)) * NHW + p0 + p4];
        sm[c][p4 + 0] = v.x; sm[c][p4 + 1] = v.y; sm[c][p4 + 2] = v.z; sm[c][p4 + 3] = v.w;
    }
    __syncthreads();
    #pragma unroll
    for (int it = 0; it < 4; it++) {
        int p = it * 16 + (tid >> 4);
        int c4 = (tid & 15) * 4;
        float4 v = make_float4(sm[c4][p], sm[c4 + 1][p], sm[c4 + 2][p], sm[c4 + 3][p]);
        *(float4*)&T[((size_t)(b * NHW + p0 + p)) * NC + c0 + c4] = v;
    }
}

// ---------------- final: out[b,c,p] = R[t][c] + P[t][c], transposed ----------------
__global__ void from_tok_add(const float* __restrict__ R, const float* __restrict__ P,
                             float* __restrict__ O) {
    __shared__ float sm[64][65];
    int p0 = blockIdx.x * 64, c0 = blockIdx.y * 64, b = blockIdx.z;
    int tid = threadIdx.x;
    #pragma unroll
    for (int it = 0; it < 4; it++) {
        int p = it * 16 + (tid >> 4);
        int c4 = (tid & 15) * 4;
        size_t row = ((size_t)(b * NHW + p0 + p)) * NC + c0 + c4;
        float4 a = *(const float4*)&R[row];
        float4 q = *(const float4*)&P[row];
        sm[c4 + 0][p] = a.x + q.x; sm[c4 + 1][p] = a.y + q.y;
        sm[c4 + 2][p] = a.z + q.z; sm[c4 + 3][p] = a.w + q.w;
    }
    __syncthreads();
    #pragma unroll
    for (int it = 0; it < 4; it++) {
        int c = it * 16 + (tid >> 4);
        int p4 = (tid & 15) * 4;
        float4 v = make_float4(sm[c][p4], sm[c][p4 + 1], sm[c][p4 + 2], sm[c][p4 + 3]);
        *(float4*)&O[((size_t)(b * NC + c0 + c)) * NHW + p0 + p4] = v;
    }
}

// ---------------- fused LN + permute (token-major rows) ----------------
// out token order: mode 0 = window, 1 = grid (forward), 2 = flat.
// T[t_out] = LN(R[flat_src(t_out)])
__global__ void ln_perm(const float* __restrict__ R, const float* __restrict__ gam,
                        const float* __restrict__ bet, float* __restrict__ T, int mode) {
    int warp = threadIdx.x >> 5, lane = threadIdx.x & 31;
    int t = blockIdx.x * 8 + warp;
    int b = t >> 14, r = t & 16383;
    int p;
    if (mode == 2) p = r;
    else {
        int win = r >> 6, pos = r & 63;
        int wy = win >> 4, wx = win & 15;
        int py = pos >> 3, px = pos & 7;
        if (mode == 0) p = (wy * 8 + py) * 128 + wx * 8 + px;
        else           p = (py * 16 + wy) * 128 + px * 16 + wx;
    }
    const float* src = R + ((size_t)b * NHW + p) * NC;
    float4 v0 = *(const float4*)(src + lane * 4);
    float4 v1 = *(const float4*)(src + 128 + lane * 4);
    float s  = v0.x + v0.y + v0.z + v0.w + v1.x + v1.y + v1.z + v1.w;
    float s2 = v0.x * v0.x + v0.y * v0.y + v0.z * v0.z + v0.w * v0.w
             + v1.x * v1.x + v1.y * v1.y + v1.z * v1.z + v1.w * v1.w;
    #pragma unroll
    for (int o = 16; o; o >>= 1) {
        s  += __shfl_xor_sync(0xffffffff, s, o);
        s2 += __shfl_xor_sync(0xffffffff, s2, o);
    }
    float m = s * (1.0f / NC);
    float rs = rsqrtf(s2 * (1.0f / NC) - m * m + 1e-5f);
    float4 g0 = *(const float4*)(gam + lane * 4);
    float4 g1 = *(const float4*)(gam + 128 + lane * 4);
    float4 b0 = *(const float4*)(bet + lane * 4);
    float4 b1 = *(const float4*)(bet + 128 + lane * 4);
    float* dst = T + (size_t)t * NC;
    float4 o0, o1;
    o0.x = (v0.x - m) * rs * g0.x + b0.x; o0.y = (v0.y - m) * rs * g0.y + b0.y;
    o0.z = (v0.z - m) * rs * g0.z + b0.z; o0.w = (v0.w - m) * rs * g0.w + b0.w;
    o1.x = (v1.x - m) * rs * g1.x + b1.x; o1.y = (v1.y - m) * rs * g1.y + b1.y;
    o1.z = (v1.z - m) * rs * g1.z + b1.z; o1.w = (v1.w - m) * rs * g1.w + b1.w;
    *(float4*)(dst + lane * 4) = o0;
    *(float4*)(dst + 128 + lane * 4) = o1;
}

// ---------------- residual add with permuted proj rows ----------------
// Rout[t_flat] = base[t_flat] + P[tok_of_flat(t_flat)]
// mode 0: window inverse; 1: grid scrambled-reverse inverse; 2: identity
__global__ void resadd_perm(const float* __restrict__ base, const float* __restrict__ P,
                            float* __restrict__ Rout, int mode) {
    int warp = threadIdx.x >> 5, lane = threadIdx.x & 31;
    int t = blockIdx.x * 8 + warp;
    int b = t >> 14, p = t & 16383;
    int h = p >> 7, w = p & 127;
    int tp;
    if (mode == 2) tp = t;
    else if (mode == 0) {
        int win = (h >> 3) * 16 + (w >> 3);
        int pos = (h & 7) * 8 + (w & 7);
        tp = (b << 14) + win * 64 + pos;
    } else {
        int K2 = h >> 3, K1 = ((h & 7) << 1) | (w >> 6);
        int S1 = (w >> 3) & 7, S2 = w & 7;
        tp = (b << 14) + (K1 * 16 + K2) * 64 + S1 * 8 + S2;
    }
    const float* pb = base + (size_t)t * NC;
    const float* pp = P + (size_t)tp * NC;
    float* po = Rout + (size_t)t * NC;
    float4 a0 = *(const float4*)(pb + lane * 4);
    float4 a1 = *(const float4*)(pb + 128 + lane * 4);
    float4 q0 = *(const float4*)(pp + lane * 4);
    float4 q1 = *(const float4*)(pp + 128 + lane * 4);
    a0.x += q0.x; a0.y += q0.y; a0.z += q0.z; a0.w += q0.w;
    a1.x += q1.x; a1.y += q1.y; a1.z += q1.z; a1.w += q1.w;
    *(float4*)(po + lane * 4) = a0;
    *(float4*)(po + 128 + lane * 4) = a1;
}

// ================= TF32 tensor-core GEMMs (software-pipelined) =================
// Block tile 128(M) x 64(N), BK=32, 8 warps (4x2), warp tile 32x32.
// SMEM: row stride 40 u32; k-chunk c at physical chunk (c ^ ((row>>2)&3));
// within chunk, pair (k, k+4) adjacent. Fragment LDS.64 conflict-free.

// ---- NT: C[M,N] = A[M,K] * B[N,K]^T + bias[n], optional exact GELU ----
template<bool GELU>
__global__ __launch_bounds__(256, 2) void gemm_tf32_nt(
        const float* __restrict__ A, const float* __restrict__ B,
        const float* __restrict__ bias, float* __restrict__ C, int N, int K) {
    __shared__ uint32_t As[128 * 40];
    __shared__ uint32_t Bs[64 * 40];
    const int tid = threadIdx.x;
    const int lane = tid & 31, warp = tid >> 5;
    const int wm = warp >> 1, wn = warp & 1;
    const int g = lane >> 2, q = lane & 3;
    const size_t m0 = (size_t)blockIdx.y * 128;
    const int n0 = blockIdx.x * 64;

    const int ar = tid >> 1;          // 0..127
    const int ach = (tid & 1) * 2;    // chunk base 0 or 2
    const int br = tid >> 2;          // 0..63
    const int bch = tid & 3;          // chunk 0..3
    const float* Ag = A + (m0 + ar) * K + ach * 8;
    const float* Bg = B + (size_t)(n0 + br) * K + bch * 8;
    const int asw = (ar >> 2) & 3;
    const int bsw = (br >> 2) & 3;
    uint32_t* Asr = As + ar * 40;
    uint32_t* Bsr = Bs + br * 40;

    float acc[2][4][4];
    #pragma unroll
    for (int i = 0; i < 2; i++)
        #pragma unroll
        for (int j = 0; j < 4; j++)
            #pragma unroll
            for (int k = 0; k < 4; k++) acc[i][j][k] = 0.0f;

    float4 aLo[2], aHi[2], bLo, bHi;
    // prologue load
    aLo[0] = *(const float4*)(Ag);      aHi[0] = *(const float4*)(Ag + 4);
    aLo[1] = *(const float4*)(Ag + 8);  aHi[1] = *(const float4*)(Ag + 12);
    bLo    = *(const float4*)(Bg);      bHi    = *(const float4*)(Bg + 4);

    for (int k0 = 0; k0 < K; k0 += 32) {
        // stage regs -> smem (with tf32 cvt)
        #pragma unroll
        for (int c = 0; c < 2; c++) {
            uint2* dst = (uint2*)(Asr + ((ach + c) ^ asw) * 8);
            dst[0] = make_uint2(f2tf(aLo[c].x), f2tf(aHi[c].x));
            dst[1] = make_uint2(f2tf(aLo[c].y), f2tf(aHi[c].y));
            dst[2] = make_uint2(f2tf(aLo[c].z), f2tf(aHi[c].z));
            dst[3] = make_uint2(f2tf(aLo[c].w), f2tf(aHi[c].w));
        }
        {
            uint2* dst = (uint2*)(Bsr + (bch ^ bsw) * 8);
            dst[0] = make_uint2(f2tf(bLo.x), f2tf(bHi.x));
            dst[1] = make_uint2(f2tf(bLo.y), f2tf(bHi.y));
            dst[2] = make_uint2(f2tf(bLo.z), f2tf(bHi.z));
            dst[3] = make_uint2(f2tf(bLo.w), f2tf(bHi.w));
        }
        __syncthreads();
        // issue next tile's global loads (latency overlaps compute)
        if (k0 + 32 < K) {
            aLo[0] = *(const float4*)(Ag + k0 + 32);      aHi[0] = *(const float4*)(Ag + k0 + 36);
            aLo[1] = *(const float4*)(Ag + k0 + 40);      aHi[1] = *(const float4*)(Ag + k0 + 44);
            bLo    = *(const float4*)(Bg + k0 + 32);      bHi    = *(const float4*)(Bg + k0 + 36);
        }
        #pragma unroll
        for (int kc = 0; kc < 4; kc++) {
            uint32_t afr[2][4], bfr[4][2];
            #pragma unroll
            for (int mt = 0; mt < 2; mt++) {
                int r0 = wm * 32 + mt * 16 + g;
                int r1 = r0 + 8;
                uint2 lo = *(uint2*)&As[r0 * 40 + ((kc ^ ((r0 >> 2) & 3)) * 8) + 2 * q];
                uint2 hi = *(uint2*)&As[r1 * 40 + ((kc ^ ((r1 >> 2) & 3)) * 8) + 2 * q];
                afr[mt][0] = lo.x; afr[mt][1] = hi.x; afr[mt][2] = lo.y; afr[mt][3] = hi.y;
            }
            #pragma unroll
            for (int nt = 0; nt < 4; nt++) {
                int rn = wn * 32 + nt * 8 + g;
                uint2 bb = *(uint2*)&Bs[rn * 40 + ((kc ^ ((rn >> 2) & 3)) * 8) + 2 * q];
                bfr[nt][0] = bb.x; bfr[nt][1] = bb.y;
            }
            #pragma unroll
            for (int mt = 0; mt < 2; mt++)
                #pragma unroll
                for (int nt = 0; nt < 4; nt++)
                    mma_tf32(acc[mt][nt], afr[mt], bfr[nt]);
        }
        __syncthreads();
    }

    #pragma unroll
    for (int mt = 0; mt < 2; mt++) {
        size_t rg = m0 + wm * 32 + mt * 16 + g;
        #pragma unroll
        for (int nt = 0; nt < 4; nt++) {
            int cb = n0 + wn * 32 + nt * 8 + 2 * q;
            float b0 = bias[cb], b1 = bias[cb + 1];
            float v0 = acc[mt][nt][0] + b0, v1 = acc[mt][nt][1] + b1;
            float v2 = acc[mt][nt][2] + b0, v3 = acc[mt][nt][3] + b1;
            if (GELU) {
                v0 = gelu_exact(v0); v1 = gelu_exact(v1);
                v2 = gelu_exact(v2); v3 = gelu_exact(v3);
            }
            *(float2*)&C[rg * N + cb] = make_float2(v0, v1);
            *(float2*)&C[(rg + 8) * N + cb] = make_float2(v2, v3);
        }
    }
}

// ---- Fuse (NN): XMtok[b*NHW+n][m] = sum_k wf[m,k]*cat[b][k,n] + bf[m] ----
// Output written token-major via smem-transposed epilogue.
__global__ __launch_bounds__(256, 2) void gemm_tf32_fuse(
        const float* __restrict__ A, const float* __restrict__ Ball,
        const float* __restrict__ biasRow, float* __restrict__ XM) {
    __shared__ char smembuf[64 * 132 * 4];   // 33792 B; unioned As/Bs + outs
    uint32_t* As = (uint32_t*)smembuf;             // 128*40
    uint32_t* Bs = As + 128 * 40;                  // 64*40
    float* outs = (float*)smembuf;                 // 64 x 132 (epilogue reuse)
    const int tid = threadIdx.x;
    const int lane = tid & 31, warp = tid >> 5;
    const int wm = warp >> 1, wn = warp & 1;
    const int g = lane >> 2, q = lane & 3;
    const int K = 768;
    const int m0 = blockIdx.y * 128;
    const int n0 = blockIdx.x * 64;
    const int b = blockIdx.z;
    const float* B = Ball + (size_t)b * 768 * NHW;

    const int ar = tid >> 1;
    const int ach = (tid & 1) * 2;
    const float* Ag = A + (size_t)(m0 + ar) * K + ach * 8;
    const int asw = (ar >> 2) & 3;
    uint32_t* Asr = As + ar * 40;

    const int fkk = tid >> 3;          // 0..31
    const int fnn = (tid & 7) * 8;     // 0..56
    const int fch = fkk >> 3;
    const int fq  = fkk & 3;
    const int fh  = (fkk >> 2) & 1;
    const float* Bgf = B + (size_t)fkk * NHW + n0 + fnn;

    float acc[2][4][4];
    #pragma unroll
    for (int i = 0; i < 2; i++)
        #pragma unroll
        for (int j = 0; j < 4; j++)
            #pragma unroll
            for (int k = 0; k < 4; k++) acc[i][j][k] = 0.0f;

    float4 aLo[2], aHi[2], bv0, bv1;
    aLo[0] = *(const float4*)(Ag);      aHi[0] = *(const float4*)(Ag + 4);
    aLo[1] = *(const float4*)(Ag + 8);  aHi[1] = *(const float4*)(Ag + 12);
    bv0 = *(const float4*)(Bgf);
    bv1 = *(const float4*)(Bgf + 4);

    for (int k0 = 0; k0 < K; k0 += 32) {
        #pragma unroll
        for (int c = 0; c < 2; c++) {
            uint2* dst = (uint2*)(Asr + ((ach + c) ^ asw) * 8);
            dst[0] = make_uint2(f2tf(aLo[c].x), f2tf(aHi[c].x));
            dst[1] = make_uint2(f2tf(aLo[c].y), f2tf(aHi[c].y));
            dst[2] = make_uint2(f2tf(aLo[c].z), f2tf(aHi[c].z));
            dst[3] = make_uint2(f2tf(aLo[c].w), f2tf(aHi[c].w));
        }
        {
            float vv[8] = {bv0.x, bv0.y, bv0.z, bv0.w, bv1.x, bv1.y, bv1.z, bv1.w};
            #pragma unroll
            for (int j = 0; j < 8; j++) {
                int n = fnn + j;
                Bs[n * 40 + ((fch ^ ((n >> 2) & 3)) * 8) + 2 * fq + fh] = f2tf(vv[j]);
            }
        }
        __syncthreads();
        if (k0 + 32 < K) {
            aLo[0] = *(const float4*)(Ag + k0 + 32);  aHi[0] = *(const float4*)(Ag + k0 + 36);
            aLo[1] = *(const float4*)(Ag + k0 + 40);  aHi[1] = *(const float4*)(Ag + k0 + 44);
            bv0 = *(const float4*)(Bgf + (size_t)(k0 + 32) * NHW);
            bv1 = *(const float4*)(Bgf + (size_t)(k0 + 32) * NHW + 4);
        }
        #pragma unroll
        for (int kc = 0; kc < 4; kc++) {
            uint32_t afr[2][4], bfr[4][2];
            #pragma unroll
            for (int mt = 0; mt < 2; mt++) {
                int r0 = wm * 32 + mt * 16 + g;
                int r1 = r0 + 8;
                uint2 lo = *(uint2*)&As[r0 * 40 + ((kc ^ ((r0 >> 2) & 3)) * 8) + 2 * q];
                uint2 hi = *(uint2*)&As[r1 * 40 + ((kc ^ ((r1 >> 2) & 3)) * 8) + 2 * q];
                afr[mt][0] = lo.x; afr[mt][1] = hi.x; afr[mt][2] = lo.y; afr[mt][3] = hi.y;
            }
            #pragma unroll
            for (int nt = 0; nt < 4; nt++) {
                int rn = wn * 32 + nt * 8 + g;
                uint2 bb = *(uint2*)&Bs[rn * 40 + ((kc ^ ((rn >> 2) & 3)) * 8) + 2 * q];
                bfr[nt][0] = bb.x; bfr[nt][1] = bb.y;
            }
            #pragma unroll
            for (int mt = 0; mt < 2; mt++)
                #pragma unroll
                for (int nt = 0; nt < 4; nt++)
                    mma_tf32(acc[mt][nt], afr[mt], bfr[nt]);
        }
        __syncthreads();
    }

    // transposed epilogue through smem: outs[col_local][row_local]
    #pragma unroll
    for (int mt = 0; mt < 2; mt++) {
        int rl = wm * 32 + mt * 16 + g;
        #pragma unroll
        for (int nt = 0; nt < 4; nt++) {
            int cl = wn * 32 + nt * 8 + 2 * q;
            outs[cl * 132 + rl]           = acc[mt][nt][0];
            outs[(cl + 1) * 132 + rl]     = acc[mt][nt][1];
            outs[cl * 132 + rl + 8]       = acc[mt][nt][2];
            outs[(cl + 1) * 132 + rl + 8] = acc[mt][nt][3];
        }
    }
    __syncthreads();
    int j = tid >> 2;               // token row 0..63
    int i0 = (tid & 3) * 32;        // channel offset
    float* dst = XM + ((size_t)(b * NHW + n0 + j)) * NC + m0 + i0;
    #pragma unroll
    for (int u = 0; u < 8; u++) {
        int i = i0 + u * 4;
        float4 v;
        v.x = outs[j * 132 + i]     + biasRow[m0 + i];
        v.y = outs[j * 132 + i + 1] + biasRow[m0 + i + 1];
        v.z = outs[j * 132 + i + 2] + biasRow[m0 + i + 2];
        v.w = outs[j * 132 + i + 3] + biasRow[m0 + i + 3];
        *(float4*)(dst + u * 4) = v;
    }
}

// ---------------- per-(window,head) attention, L=64, D=32 ----------------
__global__ void attn_kernel(const float* __restrict__ QKV, float* __restrict__ O) {
    __shared__ float sq[64 * 32], sk[64 * 32], sv[64 * 32];
    __shared__ float ss[64 * 65];
    int wh = blockIdx.x;
    int win = wh >> 3, head = wh & 7;
    int tid = threadIdx.x;
    const float* base = QKV + (size_t)win * 64 * 768 + head * 32;

    for (int i = tid; i < 512; i += 128) {
        int row = i >> 3, f4 = (i & 7) * 4;
        size_t off = (size_t)row * 768 + f4;
        *(float4*)&sq[row * 32 + f4] = *(const float4*)&base[off];
        *(float4*)&sk[row * 32 + f4] = *(const float4*)&base[off + 256];
        *(float4*)&sv[row * 32 + f4] = *(const float4*)&base[off + 512];
    }
    __syncthreads();

    int qi = tid >> 1, j0 = (tid & 1) * 32;
    float qreg[32];
    #pragma unroll
    for (int d = 0; d < 32; d++) qreg[d] = sq[qi * 32 + d];
    const float scale = 0.17677669529663687f;
    for (int j = 0; j < 32; j++) {
        int kj = j0 + j;
        float acc = 0.0f;
        #pragma unroll
        for (int d = 0; d < 32; d++) acc += qreg[d] * sk[kj * 32 + d];
        ss[qi * 65 + kj] = acc * scale;
    }
    __syncthreads();

    if (tid < 64) {
        float mx = -1e30f;
        #pragma unroll 8
        for (int j = 0; j < 64; j++) mx = fmaxf(mx, ss[tid * 65 + j]);
        float sum = 0.0f;
        #pragma unroll 8
        for (int j = 0; j < 64; j++) {
            float e = __expf(ss[tid * 65 + j] - mx);
            ss[tid * 65 + j] = e;
            sum += e;
        }
        float inv = 1.0f / sum;
        #pragma unroll 8
        for (int j = 0; j < 64; j++) ss[tid * 65 + j] *= inv;
    }
    __syncthreads();

    int d0 = (tid & 1) * 16;
    float acc[16];
    #pragma unroll
    for (int d = 0; d < 16; d++) acc[d] = 0.0f;
    for (int j = 0; j < 64; j++) {
        float pv = ss[qi * 65 + j];
        #pragma unroll
        for (int d = 0; d < 16; d++) acc[d] += pv * sv[j * 32 + d0 + d];
    }
    float* op = &O[((size_t)win * 64 + qi) * NC + head * 32 + d0];
    #pragma unroll
    for (int d = 0; d < 16; d += 4)
        *(float4*)&op[d] = make_float4(acc[d], acc[d + 1], acc[d + 2], acc[d + 3]);
}

// ---------------- launch ----------------
extern "C" void kernel_launch(void* const* d_in, const int* in_sizes, int n_in,
                              void* d_out, int out_size) {
    const float* x      = (const float*)d_in[0];
    const float* w1     = (const float*)d_in[1];
    const float* b1     = (const float*)d_in[2];
    const float* w2     = (const float*)d_in[3];
    const float* b2     = (const float*)d_in[4];
    const float* w3     = (const float*)d_in[5];
    const float* b3     = (const float*)d_in[6];
    const float* wf     = (const float*)d_in[7];
    const float* bf     = (const float*)d_in[8];
    const float* gw     = (const float*)d_in[9];
    const float* bw     = (const float*)d_in[10];
    const float* wqkv_w = (const float*)d_in[11];
    const float* bqkv_w = (const float*)d_in[12];
    const float* wo_w   = (const float*)d_in[13];
    const float* bo_w   = (const float*)d_in[14];
    const float* gg     = (const float*)d_in[15];
    const float* bg     = (const float*)d_in[16];
    const float* wqkv_g = (const float*)d_in[17];
    const float* bqkv_g = (const float*)d_in[18];
    const float* wo_g   = (const float*)d_in[19];
    const float* bo_g   = (const float*)d_in[20];
    const float* gm     = (const float*)d_in[21];
    const float* bm     = (const float*)d_in[22];
    const float* m1w    = (const float*)d_in[23];
    const float* m1b    = (const float*)d_in[24];
    const float* m2w    = (const float*)d_in[25];
    const float* m2b    = (const float*)d_in[26];
    float* out = (float*)d_out;

    void *p_cat, *p_xm, *p_xtok, *p_tok, *p_qkv, *p_att, *p_proj, *p_h1;
    cudaGetSymbolAddress(&p_cat, g_cat);
    cudaGetSymbolAddress(&p_xm, g_xm);
    cudaGetSymbolAddress(&p_xtok, g_xtok);
    cudaGetSymbolAddress(&p_tok, g_tok);
    cudaGetSymbolAddress(&p_qkv, g_qkv);
    cudaGetSymbolAddress(&p_att, g_att);
    cudaGetSymbolAddress(&p_proj, g_proj);
    cudaGetSymbolAddress(&p_h1, g_h1);
    float* cat  = (float*)p_cat;   float* xm   = (float*)p_xm;
    float* xtok = (float*)p_xtok;  float* tok  = (float*)p_tok;
    float* qkv  = (float*)p_qkv;   float* att  = (float*)p_att;
    float* proj = (float*)p_proj;  float* h1   = (float*)p_h1;

    // depthwise convs -> cat; input transpose to token-major
    dwconv3_kernel<<<dim3(16, NC, NB), 256>>>(x, w1, b1, w2, b2, w3, b3);
    to_tok<<<dim3(256, 4, NB), 256>>>(x, xtok);
    // 1x1 fuse -> xm (token-major)
    gemm_tf32_fuse<<<dim3(256, 2, NB), 256>>>(wf, cat, bf, xm);

    // ---- window branch ----
    ln_perm<<<16384, 256>>>(xm, gw, bw, tok, 0);
    gemm_tf32_nt<false><<<dim3(12, 1024), 256>>>(tok, wqkv_w, bqkv_w, qkv, 768, 256);
    attn_kernel<<<16384, 128>>>(qkv, att);
    gemm_tf32_nt<false><<<dim3(4, 1024), 256>>>(att, wo_w, bo_w, proj, 256, 256);
    resadd_perm<<<16384, 256>>>(xtok, proj, xm, 0);

    // ---- grid branch ----
    ln_perm<<<16384, 256>>>(xm, gg, bg, tok, 1);
    gemm_tf32_nt<false><<<dim3(12, 1024), 256>>>(tok, wqkv_g, bqkv_g, qkv, 768, 256);
    attn_kernel<<<16384, 128>>>(qkv, att);
    gemm_tf32_nt<false><<<dim3(4, 1024), 256>>>(att, wo_g, bo_g, proj, 256, 256);
    resadd_perm<<<16384, 256>>>(xm, proj, xm, 1);

    // ---- MLP ----
    ln_perm<<<16384, 256>>>(xm, gm, bm, tok, 2);
    gemm_tf32_nt<true ><<<dim3(16, 1024), 256>>>(tok, m1w, m1b, h1, 1024, 256);
    gemm_tf32_nt<false><<<dim3(4, 1024), 256>>>(h1, m2w, m2b, proj, 256, 1024);
    from_tok_add<<<dim3(256, 4, NB), 256>>>(xm, proj, out);
}

// round 5
// speedup vs baseline: 3.1179x; 1.5151x over previous
#include <cuda_runtime.h>
#include <cuda_bf16.h>
#include <math.h>
#include <stdint.h>

// ---------------- problem constants ----------------
#define NB   8
#define NC   256
#define NHW  16384     // 128*128
#define NTOK 131072    // NB*NHW

typedef __nv_bfloat16 bf16;

// ---------------- scratch (device globals) ----------------
__device__ bf16  g_cat [(size_t)NB * 768 * NHW];   // [B,3C,HW] bf16
__device__ bf16  g_catt[(size_t)NTOK * 768];       // cat token-major bf16
__device__ float g_xm  [(size_t)NTOK * NC];        // residual stream (fp32)
__device__ float g_xtok[(size_t)NTOK * NC];        // x token-major (fp32)
__device__ bf16  g_tok [(size_t)NTOK * NC];        // LN'd tokens bf16
__device__ bf16  g_qkv [(size_t)NTOK * 768];
__device__ bf16  g_att [(size_t)NTOK * NC];
__device__ float g_proj[(size_t)NTOK * NC];
__device__ bf16  g_h1  [(size_t)NTOK * 1024];
__device__ bf16  g_wb  [1245184];                  // all weights converted to bf16

// weight offsets in g_wb
#define OFF_WF   0
#define OFF_QKVW 196608
#define OFF_QKVG 393216
#define OFF_WOW  589824
#define OFF_WOG  655360
#define OFF_M1   720896
#define OFF_M2   983040

// ---------------- helpers ----------------
__device__ __forceinline__ float gelu_exact(float x) {
    return 0.5f * x * (1.0f + erff(x * 0.70710678118654752f));
}
__device__ __forceinline__ float2 bf2f(uint32_t w) {
    __nv_bfloat162 h = *reinterpret_cast<__nv_bfloat162*>(&w);
    return __bfloat1622float2(h);
}
__device__ __forceinline__ uint32_t f2bf2(float a, float b) {
    __nv_bfloat162 h = __floats2bfloat162_rn(a, b);
    return *reinterpret_cast<uint32_t*>(&h);
}
__device__ __forceinline__ void mma_bf16(float* d, const uint32_t* a, const uint32_t* b) {
    asm volatile(
        "mma.sync.aligned.m16n8k16.row.col.f32.bf16.bf16.f32 "
        "{%0,%1,%2,%3}, {%4,%5,%6,%7}, {%8,%9}, {%0,%1,%2,%3};"
        : "+f"(d[0]), "+f"(d[1]), "+f"(d[2]), "+f"(d[3])
        : "r"(a[0]), "r"(a[1]), "r"(a[2]), "r"(a[3]), "r"(b[0]), "r"(b[1]));
}

// ---------------- weight fp32 -> bf16 (vectorized x4) ----------------
__global__ void cvt_w(const float* __restrict__ s, bf16* __restrict__ d, int n4) {
    int i = blockIdx.x * 256 + threadIdx.x;
    if (i < n4) {
        float4 v = *(const float4*)(s + i * 4);
        uint2 o = make_uint2(f2bf2(v.x, v.y), f2bf2(v.z, v.w));
        *(uint2*)(d + i * 4) = o;
    }
}

// ---------------- 1) fused depthwise convs (3x3,5x5,7x7) -> bf16 cat ----------------
__global__ void dwconv3_kernel(const float* __restrict__ X,
                               const float* __restrict__ w1, const float* __restrict__ b1,
                               const float* __restrict__ w2, const float* __restrict__ b2,
                               const float* __restrict__ w3, const float* __restrict__ b3) {
    __shared__ float sx[38][39];
    __shared__ float swt[83];
    int c = blockIdx.y, b = blockIdx.z;
    int tile = blockIdx.x;
    int ty0 = (tile >> 2) * 32, tx0 = (tile & 3) * 32;
    const float* Xp = X + ((size_t)b * NC + c) * NHW;
    int tid = threadIdx.x;

    if (tid < 9)       swt[tid] = w1[c * 9 + tid];
    else if (tid < 34) swt[tid] = w2[c * 25 + (tid - 9)];
    else if (tid < 83) swt[tid] = w3[c * 49 + (tid - 34)];

    for (int i = tid; i < 38 * 38; i += 256) {
        int iy = i / 38, ix = i - iy * 38;
        int gy = ty0 + iy - 3, gx = tx0 + ix - 3;
        float v = 0.0f;
        if (gy >= 0 && gy < 128 && gx >= 0 && gx < 128) v = Xp[gy * 128 + gx];
        sx[iy][ix] = v;
    }
    __syncthreads();

    float bb1 = b1[c], bb2 = b2[c], bb3 = b3[c];
    size_t ob1 = ((size_t)b * 768 + c) * NHW;
    size_t ob2 = ((size_t)b * 768 + 256 + c) * NHW;
    size_t ob3 = ((size_t)b * 768 + 512 + c) * NHW;

    #pragma unroll
    for (int sub = 0; sub < 4; sub++) {
        int oy = (tid >> 5) + sub * 8;
        int ox = (tid & 31);
        int cy = oy + 3, cx = ox + 3;
        float a1 = bb1, a2 = bb2, a3 = bb3;
        #pragma unroll
        for (int dy = -3; dy <= 3; dy++) {
            #pragma unroll
            for (int dx = -3; dx <= 3; dx++) {
                float v = sx[cy + dy][cx + dx];
                a3 += v * swt[34 + (dy + 3) * 7 + (dx + 3)];
                if (dy >= -2 && dy <= 2 && dx >= -2 && dx <= 2)
                    a2 += v * swt[9 + (dy + 2) * 5 + (dx + 2)];
                if (dy >= -1 && dy <= 1 && dx >= -1 && dx <= 1)
                    a1 += v * swt[(dy + 1) * 3 + (dx + 1)];
            }
        }
        int po = (ty0 + oy) * 128 + tx0 + ox;
        g_cat[ob1 + po] = __float2bfloat16_rn(a1);
        g_cat[ob2 + po] = __float2bfloat16_rn(a2);
        g_cat[ob3 + po] = __float2bfloat16_rn(a3);
    }
}

// ---------------- cat [b][k][p] -> cat_t [b*NHW+p][k] (bf16 transpose) ----------------
__global__ void cat_transpose(const bf16* __restrict__ S, bf16* __restrict__ D) {
    __shared__ bf16 sm[64][66];
    int p0 = blockIdx.x * 64, k0 = blockIdx.y * 64, b = blockIdx.z;
    int tid = threadIdx.x;
    {
        int k = tid >> 2;
        int pc = (tid & 3) * 16;
        const bf16* src = S + ((size_t)(b * 768 + k0 + k)) * NHW + p0 + pc;
        uint4 v0 = *(const uint4*)src;
        uint4 v1 = *(const uint4*)(src + 8);
        uint32_t* dst = (uint32_t*)&sm[k][pc];   // 4B-aligned (132*k + 2*pc)
        dst[0] = v0.x; dst[1] = v0.y; dst[2] = v0.z; dst[3] = v0.w;
        dst[4] = v1.x; dst[5] = v1.y; dst[6] = v1.z; dst[7] = v1.w;
    }
    __syncthreads();
    {
        int p = tid >> 2;
        int kc = (tid & 3) * 16;
        uint32_t w[8];
        #pragma unroll
        for (int j = 0; j < 8; j++) {
            bf16 lo = sm[kc + 2 * j][p];
            bf16 hi = sm[kc + 2 * j + 1][p];
            __nv_bfloat162 h2 = __halves2bfloat162(lo, hi);
            w[j] = *reinterpret_cast<uint32_t*>(&h2);
        }
        bf16* dst = D + ((size_t)(b * NHW + p0 + p)) * 768 + k0 + kc;
        *(uint4*)dst = make_uint4(w[0], w[1], w[2], w[3]);
        *(uint4*)(dst + 8) = make_uint4(w[4], w[5], w[6], w[7]);
    }
}

// ---------------- transpose x [B,C,HW] -> token-major fp32 ----------------
__global__ void to_tok(const float* __restrict__ X, float* __restrict__ T) {
    __shared__ float sm[64][65];
    int p0 = blockIdx.x * 64, c0 = blockIdx.y * 64, b = blockIdx.z;
    int tid = threadIdx.x;
    #pragma unroll
    for (int it = 0; it < 4; it++) {
        int c = it * 16 + (tid >> 4);
        int p4 = (tid & 15) * 4;
        float4 v = *(const float4*)&X[((size_t)(b * NC + c0 + c)) * NHW + p0 + p4];
        sm[c][p4 + 0] = v.x; sm[c][p4 + 1] = v.y; sm[c][p4 + 2] = v.z; sm[c][p4 + 3] = v.w;
    }
    __syncthreads();
    #pragma unroll
    for (int it = 0; it < 4; it++) {
        int p = it * 16 + (tid >> 4);
        int c4 = (tid & 15) * 4;
        float4 v = make_float4(sm[c4][p], sm[c4 + 1][p], sm[c4 + 2][p], sm[c4 + 3][p]);
        *(float4*)&T[((size_t)(b * NHW + p0 + p)) * NC + c0 + c4] = v;
    }
}

// ---------------- final: out[b,c,p] = R[t][c] + P[t][c], transposed ----------------
__global__ void from_tok_add(const float* __restrict__ R, const float* __restrict__ P,
                             float* __restrict__ O) {
    __shared__ float sm[64][65];
    int p0 = blockIdx.x * 64, c0 = blockIdx.y * 64, b = blockIdx.z;
    int tid = threadIdx.x;
    #pragma unroll
    for (int it = 0; it < 4; it++) {
        int p = it * 16 + (tid >> 4);
        int c4 = (tid & 15) * 4;
        size_t row = ((size_t)(b * NHW + p0 + p)) * NC + c0 + c4;
        float4 a = *(const float4*)&R[row];
        float4 q = *(const float4*)&P[row];
        sm[c4 + 0][p] = a.x + q.x; sm[c4 + 1][p] = a.y + q.y;
        sm[c4 + 2][p] = a.z + q.z; sm[c4 + 3][p] = a.w + q.w;
    }
    __syncthreads();
    #pragma unroll
    for (int it = 0; it < 4; it++) {
        int c = it * 16 + (tid >> 4);
        int p4 = (tid & 15) * 4;
        float4 v = make_float4(sm[c][p4], sm[c][p4 + 1], sm[c][p4 + 2], sm[c][p4 + 3]);
        *(float4*)&O[((size_t)(b * NC + c0 + c)) * NHW + p0 + p4] = v;
    }
}

// ---------------- fused LN + permute -> bf16 tokens ----------------
__global__ void ln_perm(const float* __restrict__ R, const float* __restrict__ gam,
                        const float* __restrict__ bet, bf16* __restrict__ T, int mode) {
    int warp = threadIdx.x >> 5, lane = threadIdx.x & 31;
    int t = blockIdx.x * 8 + warp;
    int b = t >> 14, r = t & 16383;
    int p;
    if (mode == 2) p = r;
    else {
        int win = r >> 6, pos = r & 63;
        int wy = win >> 4, wx = win & 15;
        int py = pos >> 3, px = pos & 7;
        if (mode == 0) p = (wy * 8 + py) * 128 + wx * 8 + px;
        else           p = (py * 16 + wy) * 128 + px * 16 + wx;
    }
    const float* src = R + ((size_t)b * NHW + p) * NC;
    float4 v0 = *(const float4*)(src + lane * 4);
    float4 v1 = *(const float4*)(src + 128 + lane * 4);
    float s  = v0.x + v0.y + v0.z + v0.w + v1.x + v1.y + v1.z + v1.w;
    float s2 = v0.x * v0.x + v0.y * v0.y + v0.z * v0.z + v0.w * v0.w
             + v1.x * v1.x + v1.y * v1.y + v1.z * v1.z + v1.w * v1.w;
    #pragma unroll
    for (int o = 16; o; o >>= 1) {
        s  += __shfl_xor_sync(0xffffffff, s, o);
        s2 += __shfl_xor_sync(0xffffffff, s2, o);
    }
    float m = s * (1.0f / NC);
    float rs = rsqrtf(s2 * (1.0f / NC) - m * m + 1e-5f);
    float4 g0 = *(const float4*)(gam + lane * 4);
    float4 g1 = *(const float4*)(gam + 128 + lane * 4);
    float4 b0 = *(const float4*)(bet + lane * 4);
    float4 b1 = *(const float4*)(bet + 128 + lane * 4);
    bf16* dst = T + (size_t)t * NC;
    float o0x = (v0.x - m) * rs * g0.x + b0.x, o0y = (v0.y - m) * rs * g0.y + b0.y;
    float o0z = (v0.z - m) * rs * g0.z + b0.z, o0w = (v0.w - m) * rs * g0.w + b0.w;
    float o1x = (v1.x - m) * rs * g1.x + b1.x, o1y = (v1.y - m) * rs * g1.y + b1.y;
    float o1z = (v1.z - m) * rs * g1.z + b1.z, o1w = (v1.w - m) * rs * g1.w + b1.w;
    *(uint2*)(dst + lane * 4)       = make_uint2(f2bf2(o0x, o0y), f2bf2(o0z, o0w));
    *(uint2*)(dst + 128 + lane * 4) = make_uint2(f2bf2(o1x, o1y), f2bf2(o1z, o1w));
}

// ---------------- residual add with permuted proj rows (fp32) ----------------
__global__ void resadd_perm(const float* __restrict__ base, const float* __restrict__ P,
                            float* __restrict__ Rout, int mode) {
    int warp = threadIdx.x >> 5, lane = threadIdx.x & 31;
    int t = blockIdx.x * 8 + warp;
    int b = t >> 14, p = t & 16383;
    int h = p >> 7, w = p & 127;
    int tp;
    if (mode == 2) tp = t;
    else if (mode == 0) {
        int win = (h >> 3) * 16 + (w >> 3);
        int pos = (h & 7) * 8 + (w & 7);
        tp = (b << 14) + win * 64 + pos;
    } else {
        int K2 = h >> 3, K1 = ((h & 7) << 1) | (w >> 6);
        int S1 = (w >> 3) & 7, S2 = w & 7;
        tp = (b << 14) + (K1 * 16 + K2) * 64 + S1 * 8 + S2;
    }
    const float* pb = base + (size_t)t * NC;
    const float* pp = P + (size_t)tp * NC;
    float* po = Rout + (size_t)t * NC;
    float4 a0 = *(const float4*)(pb + lane * 4);
    float4 a1 = *(const float4*)(pb + 128 + lane * 4);
    float4 q0 = *(const float4*)(pp + lane * 4);
    float4 q1 = *(const float4*)(pp + 128 + lane * 4);
    a0.x += q0.x; a0.y += q0.y; a0.z += q0.z; a0.w += q0.w;
    a1.x += q1.x; a1.y += q1.y; a1.z += q1.z; a1.w += q1.w;
    *(float4*)(po + lane * 4) = a0;
    *(float4*)(po + 128 + lane * 4) = a1;
}

// ================= bf16 tensor-core NT GEMM =================
// C[M,N] = A[M,K] * B[N,K]^T + bias[n]; 128x64 tile, BK=64, 8 warps (4x2).
// SMEM row = 32 u32 (64 bf16) in 4 chunks of 8 words; chunk c stored at
// (c ^ ((row>>2)&3)); within chunk, word order pairs (j, j+4) interleaved so
// LDS.64 at word 2q yields {pair q, pair q+4}. Row stride 40 u32.
template<typename OutT, bool GELU>
__global__ __launch_bounds__(256, 2) void gemm_bf16_nt(
        const bf16* __restrict__ A, const bf16* __restrict__ B,
        const float* __restrict__ bias, OutT* __restrict__ C, int N, int K) {
    __shared__ uint32_t As[128 * 40];
    __shared__ uint32_t Bs[64 * 40];
    const int tid = threadIdx.x;
    const int lane = tid & 31, warp = tid >> 5;
    const int wm = warp >> 1, wn = warp & 1;
    const int g = lane >> 2, q = lane & 3;
    const size_t m0 = (size_t)blockIdx.y * 128;
    const int n0 = blockIdx.x * 64;

    const int ar = tid >> 1;          // 0..127
    const int ach = (tid & 1) * 2;    // chunks {0,1} or {2,3}
    const int br = tid >> 2;          // 0..63
    const int bch = tid & 3;          // chunk 0..3
    const bf16* Ag = A + (m0 + ar) * K + ach * 16;
    const bf16* Bg = B + (size_t)(n0 + br) * K + bch * 16;
    const int asw = (ar >> 2) & 3;
    const int bsw = (br >> 2) & 3;
    uint32_t* Asr = As + ar * 40;
    uint32_t* Bsr = Bs + br * 40;

    float acc[2][4][4];
    #pragma unroll
    for (int i = 0; i < 2; i++)
        #pragma unroll
        for (int j = 0; j < 4; j++)
            #pragma unroll
            for (int k = 0; k < 4; k++) acc[i][j][k] = 0.0f;

    uint4 aR[4], bR[2];
    {
        const uint4* Ap = (const uint4*)Ag;
        aR[0] = Ap[0]; aR[1] = Ap[1]; aR[2] = Ap[2]; aR[3] = Ap[3];
        const uint4* Bp = (const uint4*)Bg;
        bR[0] = Bp[0]; bR[1] = Bp[1];
    }

    for (int k0 = 0; k0 < K; k0 += 64) {
        // stage regs -> smem (pure bit movement)
        #pragma unroll
        for (int c = 0; c < 2; c++) {
            uint4 lo = aR[2 * c], hi = aR[2 * c + 1];
            uint2* dst = (uint2*)(Asr + ((ach + c) ^ asw) * 8);
            dst[0] = make_uint2(lo.x, hi.x);
            dst[1] = make_uint2(lo.y, hi.y);
            dst[2] = make_uint2(lo.z, hi.z);
            dst[3] = make_uint2(lo.w, hi.w);
        }
        {
            uint2* dst = (uint2*)(Bsr + (bch ^ bsw) * 8);
            dst[0] = make_uint2(bR[0].x, bR[1].x);
            dst[1] = make_uint2(bR[0].y, bR[1].y);
            dst[2] = make_uint2(bR[0].z, bR[1].z);
            dst[3] = make_uint2(bR[0].w, bR[1].w);
        }
        __syncthreads();
        // prefetch next BK tile (overlaps mma phase)
        if (k0 + 64 < K) {
            const uint4* Ap = (const uint4*)(Ag + k0 + 64);
            aR[0] = Ap[0]; aR[1] = Ap[1]; aR[2] = Ap[2]; aR[3] = Ap[3];
            const uint4* Bp = (const uint4*)(Bg + k0 + 64);
            bR[0] = Bp[0]; bR[1] = Bp[1];
        }
        #pragma unroll
        for (int kc = 0; kc < 4; kc++) {
            uint32_t afr[2][4], bfr[4][2];
            #pragma unroll
            for (int mt = 0; mt < 2; mt++) {
                int r0 = wm * 32 + mt * 16 + g;
                int r1 = r0 + 8;
                uint2 lo = *(uint2*)&As[r0 * 40 + ((kc ^ ((r0 >> 2) & 3)) * 8) + 2 * q];
                uint2 hi = *(uint2*)&As[r1 * 40 + ((kc ^ ((r1 >> 2) & 3)) * 8) + 2 * q];
                afr[mt][0] = lo.x; afr[mt][1] = hi.x; afr[mt][2] = lo.y; afr[mt][3] = hi.y;
            }
            #pragma unroll
            for (int nt = 0; nt < 4; nt++) {
                int rn = wn * 32 + nt * 8 + g;
                uint2 bb = *(uint2*)&Bs[rn * 40 + ((kc ^ ((rn >> 2) & 3)) * 8) + 2 * q];
                bfr[nt][0] = bb.x; bfr[nt][1] = bb.y;
            }
            #pragma unroll
            for (int mt = 0; mt < 2; mt++)
                #pragma unroll
                for (int nt = 0; nt < 4; nt++)
                    mma_bf16(acc[mt][nt], afr[mt], bfr[nt]);
        }
        __syncthreads();
    }

    #pragma unroll
    for (int mt = 0; mt < 2; mt++) {
        size_t rg = m0 + wm * 32 + mt * 16 + g;
        #pragma unroll
        for (int nt = 0; nt < 4; nt++) {
            int cb = n0 + wn * 32 + nt * 8 + 2 * q;
            float b0 = bias[cb], b1 = bias[cb + 1];
            float v0 = acc[mt][nt][0] + b0, v1 = acc[mt][nt][1] + b1;
            float v2 = acc[mt][nt][2] + b0, v3 = acc[mt][nt][3] + b1;
            if (GELU) {
                v0 = gelu_exact(v0); v1 = gelu_exact(v1);
                v2 = gelu_exact(v2); v3 = gelu_exact(v3);
            }
            if constexpr (sizeof(OutT) == 4) {
                *(float2*)&((float*)C)[rg * N + cb] = make_float2(v0, v1);
                *(float2*)&((float*)C)[(rg + 8) * N + cb] = make_float2(v2, v3);
            } else {
                *(uint32_t*)&((bf16*)C)[rg * N + cb] = f2bf2(v0, v1);
                *(uint32_t*)&((bf16*)C)[(rg + 8) * N + cb] = f2bf2(v2, v3);
            }
        }
    }
}

// ---------------- per-(window,head) attention, L=64, D=32 (bf16 I/O) ----------------
__global__ void attn_kernel(const bf16* __restrict__ QKV, bf16* __restrict__ O) {
    __shared__ float sq[64 * 32], sk[64 * 32], sv[64 * 32];
    __shared__ float ss[64 * 65];
    int wh = blockIdx.x;
    int win = wh >> 3, head = wh & 7;
    int tid = threadIdx.x;
    const bf16* base = QKV + (size_t)win * 64 * 768 + head * 32;

    for (int i = tid; i < 256; i += 128) {
        int row = i >> 2, c8 = (i & 3) * 8;
        size_t off = (size_t)row * 768 + c8;
        uint4 qw = *(const uint4*)(base + off);
        uint4 kw = *(const uint4*)(base + off + 256);
        uint4 vw = *(const uint4*)(base + off + 512);
        float2 a, b2, c2, d2;
        a = bf2f(qw.x); b2 = bf2f(qw.y); c2 = bf2f(qw.z); d2 = bf2f(qw.w);
        *(float4*)&sq[row * 32 + c8]     = make_float4(a.x, a.y, b2.x, b2.y);
        *(float4*)&sq[row * 32 + c8 + 4] = make_float4(c2.x, c2.y, d2.x, d2.y);
        a = bf2f(kw.x); b2 = bf2f(kw.y); c2 = bf2f(kw.z); d2 = bf2f(kw.w);
        *(float4*)&sk[row * 32 + c8]     = make_float4(a.x, a.y, b2.x, b2.y);
        *(float4*)&sk[row * 32 + c8 + 4] = make_float4(c2.x, c2.y, d2.x, d2.y);
        a = bf2f(vw.x); b2 = bf2f(vw.y); c2 = bf2f(vw.z); d2 = bf2f(vw.w);
        *(float4*)&sv[row * 32 + c8]     = make_float4(a.x, a.y, b2.x, b2.y);
        *(float4*)&sv[row * 32 + c8 + 4] = make_float4(c2.x, c2.y, d2.x, d2.y);
    }
    __syncthreads();

    int qi = tid >> 1, j0 = (tid & 1) * 32;
    float qreg[32];
    #pragma unroll
    for (int d = 0; d < 32; d++) qreg[d] = sq[qi * 32 + d];
    const float scale = 0.17677669529663687f;
    for (int j = 0; j < 32; j++) {
        int kj = j0 + j;
        float acc = 0.0f;
        #pragma unroll
        for (int d = 0; d < 32; d++) acc += qreg[d] * sk[kj * 32 + d];
        ss[qi * 65 + kj] = acc * scale;
    }
    __syncthreads();

    if (tid < 64) {
        float mx = -1e30f;
        #pragma unroll 8
        for (int j = 0; j < 64; j++) mx = fmaxf(mx, ss[tid * 65 + j]);
        float sum = 0.0f;
        #pragma unroll 8
        for (int j = 0; j < 64; j++) {
            float e = __expf(ss[tid * 65 + j] - mx);
            ss[tid * 65 + j] = e;
            sum += e;
        }
        float inv = 1.0f / sum;
        #pragma unroll 8
        for (int j = 0; j < 64; j++) ss[tid * 65 + j] *= inv;
    }
    __syncthreads();

    int d0 = (tid & 1) * 16;
    float acc[16];
    #pragma unroll
    for (int d = 0; d < 16; d++) acc[d] = 0.0f;
    for (int j = 0; j < 64; j++) {
        float pv = ss[qi * 65 + j];
        #pragma unroll
        for (int d = 0; d < 16; d++) acc[d] += pv * sv[j * 32 + d0 + d];
    }
    bf16* op = &O[((size_t)win * 64 + qi) * NC + head * 32 + d0];
    uint32_t w[8];
    #pragma unroll
    for (int j = 0; j < 8; j++) w[j] = f2bf2(acc[2 * j], acc[2 * j + 1]);
    *(uint4*)op = make_uint4(w[0], w[1], w[2], w[3]);
    *(uint4*)(op + 8) = make_uint4(w[4], w[5], w[6], w[7]);
}

// ---------------- launch ----------------
extern "C" void kernel_launch(void* const* d_in, const int* in_sizes, int n_in,
                              void* d_out, int out_size) {
    const float* x      = (const float*)d_in[0];
    const float* w1     = (const float*)d_in[1];
    const float* b1     = (const float*)d_in[2];
    const float* w2     = (const float*)d_in[3];
    const float* b2     = (const float*)d_in[4];
    const float* w3     = (const float*)d_in[5];
    const float* b3     = (const float*)d_in[6];
    const float* wf     = (const float*)d_in[7];
    const float* bf     = (const float*)d_in[8];
    const float* gw     = (const float*)d_in[9];
    const float* bw     = (const float*)d_in[10];
    const float* wqkv_w = (const float*)d_in[11];
    const float* bqkv_w = (const float*)d_in[12];
    const float* wo_w   = (const float*)d_in[13];
    const float* bo_w   = (const float*)d_in[14];
    const float* gg     = (const float*)d_in[15];
    const float* bg     = (const float*)d_in[16];
    const float* wqkv_g = (const float*)d_in[17];
    const float* bqkv_g = (const float*)d_in[18];
    const float* wo_g   = (const float*)d_in[19];
    const float* bo_g   = (const float*)d_in[20];
    const float* gm     = (const float*)d_in[21];
    const float* bm     = (const float*)d_in[22];
    const float* m1w    = (const float*)d_in[23];
    const float* m1b    = (const float*)d_in[24];
    const float* m2w    = (const float*)d_in[25];
    const float* m2b    = (const float*)d_in[26];
    float* out = (float*)d_out;

    void *p_cat, *p_catt, *p_xm, *p_xtok, *p_tok, *p_qkv, *p_att, *p_proj, *p_h1, *p_wb;
    cudaGetSymbolAddress(&p_cat, g_cat);
    cudaGetSymbolAddress(&p_catt, g_catt);
    cudaGetSymbolAddress(&p_xm, g_xm);
    cudaGetSymbolAddress(&p_xtok, g_xtok);
    cudaGetSymbolAddress(&p_tok, g_tok);
    cudaGetSymbolAddress(&p_qkv, g_qkv);
    cudaGetSymbolAddress(&p_att, g_att);
    cudaGetSymbolAddress(&p_proj, g_proj);
    cudaGetSymbolAddress(&p_h1, g_h1);
    cudaGetSymbolAddress(&p_wb, g_wb);
    bf16* cat  = (bf16*)p_cat;    bf16* catt = (bf16*)p_catt;
    float* xm  = (float*)p_xm;    float* xtok = (float*)p_xtok;
    bf16* tok  = (bf16*)p_tok;    bf16* qkv  = (bf16*)p_qkv;
    bf16* att  = (bf16*)p_att;    float* proj = (float*)p_proj;
    bf16* h1   = (bf16*)p_h1;     bf16* wb   = (bf16*)p_wb;

    // weight conversions (bf16)
    cvt_w<<<192, 256>>>(wf,     wb + OFF_WF,   49152);
    cvt_w<<<192, 256>>>(wqkv_w, wb + OFF_QKVW, 49152);
    cvt_w<<<192, 256>>>(wqkv_g, wb + OFF_QKVG, 49152);
    cvt_w<<<64,  256>>>(wo_w,   wb + OFF_WOW,  16384);
    cvt_w<<<64,  256>>>(wo_g,   wb + OFF_WOG,  16384);
    cvt_w<<<256, 256>>>(m1w,    wb + OFF_M1,   65536);
    cvt_w<<<256, 256>>>(m2w,    wb + OFF_M2,   65536);

    // depthwise convs -> cat (bf16); transpose to token-major; x -> token-major
    dwconv3_kernel<<<dim3(16, NC, NB), 256>>>(x, w1, b1, w2, b2, w3, b3);
    cat_transpose<<<dim3(256, 12, NB), 256>>>(cat, catt);
    to_tok<<<dim3(256, 4, NB), 256>>>(x, xtok);

    // 1x1 fuse as NT GEMM -> xm (fp32, token-major)
    gemm_bf16_nt<float, false><<<dim3(4, 1024), 256>>>(catt, wb + OFF_WF, bf, xm, 256, 768);

    // ---- window branch ----
    ln_perm<<<16384, 256>>>(xm, gw, bw, tok, 0);
    gemm_bf16_nt<bf16, false><<<dim3(12, 1024), 256>>>(tok, wb + OFF_QKVW, bqkv_w, qkv, 768, 256);
    attn_kernel<<<16384, 128>>>(qkv, att);
    gemm_bf16_nt<float, false><<<dim3(4, 1024), 256>>>(att, wb + OFF_WOW, bo_w, proj, 256, 256);
    resadd_perm<<<16384, 256>>>(xtok, proj, xm, 0);

    // ---- grid branch ----
    ln_perm<<<16384, 256>>>(xm, gg, bg, tok, 1);
    gemm_bf16_nt<bf16, false><<<dim3(12, 1024), 256>>>(tok, wb + OFF_QKVG, bqkv_g, qkv, 768, 256);
    attn_kernel<<<16384, 128>>>(qkv, att);
    gemm_bf16_nt<float, false><<<dim3(4, 1024), 256>>>(att, wb + OFF_WOG, bo_g, proj, 256, 256);
    resadd_perm<<<16384, 256>>>(xm, proj, xm, 1);

    // ---- MLP ----
    ln_perm<<<16384, 256>>>(xm, gm, bm, tok, 2);
    gemm_bf16_nt<bf16, true ><<<dim3(16, 1024), 256>>>(tok, wb + OFF_M1, m1b, h1, 1024, 256);
    gemm_bf16_nt<float, false><<<dim3(4, 1024), 256>>>(h1, wb + OFF_M2, m2b, proj, 256, 1024);
    from_tok_add<<<dim3(256, 4, NB), 256>>>(xm, proj, out);
}

// round 6
// speedup vs baseline: 4.0591x; 1.3019x over previous
#include <cuda_runtime.h>
#include <cuda_bf16.h>
#include <math.h>
#include <stdint.h>

// ---------------- problem constants ----------------
#define NB   8
#define NC   256
#define NHW  16384     // 128*128
#define NTOK 131072    // NB*NHW

typedef __nv_bfloat16 bf16;

// ---------------- scratch (device globals) ----------------
__device__ bf16  g_cat [(size_t)NB * 768 * NHW];   // [B,3C,HW] bf16
__device__ bf16  g_catt[(size_t)NTOK * 768];       // cat token-major bf16
__device__ float g_xm  [(size_t)NTOK * NC];        // residual stream (fp32)
__device__ float g_xtok[(size_t)NTOK * NC];        // x token-major (fp32)
__device__ bf16  g_tok [(size_t)NTOK * NC];        // LN'd tokens bf16
__device__ bf16  g_qkv [(size_t)NTOK * 768];
__device__ bf16  g_att [(size_t)NTOK * NC];
__device__ float g_proj[(size_t)NTOK * NC];
__device__ bf16  g_h1  [(size_t)NTOK * 1024];
__device__ bf16  g_wb  [1245184];                  // all weights converted to bf16

// weight offsets in g_wb
#define OFF_WF   0
#define OFF_QKVW 196608
#define OFF_QKVG 393216
#define OFF_WOW  589824
#define OFF_WOG  655360
#define OFF_M1   720896
#define OFF_M2   983040

// ---------------- helpers ----------------
__device__ __forceinline__ float gelu_exact(float x) {
    return 0.5f * x * (1.0f + erff(x * 0.70710678118654752f));
}
__device__ __forceinline__ uint32_t f2bf2(float a, float b) {
    __nv_bfloat162 h = __floats2bfloat162_rn(a, b);
    return *reinterpret_cast<uint32_t*>(&h);
}
__device__ __forceinline__ void mma_bf16(float* d, const uint32_t* a, const uint32_t* b) {
    asm volatile(
        "mma.sync.aligned.m16n8k16.row.col.f32.bf16.bf16.f32 "
        "{%0,%1,%2,%3}, {%4,%5,%6,%7}, {%8,%9}, {%0,%1,%2,%3};"
        : "+f"(d[0]), "+f"(d[1]), "+f"(d[2]), "+f"(d[3])
        : "r"(a[0]), "r"(a[1]), "r"(a[2]), "r"(a[3]), "r"(b[0]), "r"(b[1]));
}

// ---------------- weight fp32 -> bf16 (vectorized x4) ----------------
__global__ void cvt_w(const float* __restrict__ s, bf16* __restrict__ d, int n4) {
    int i = blockIdx.x * 256 + threadIdx.x;
    if (i < n4) {
        float4 v = *(const float4*)(s + i * 4);
        uint2 o = make_uint2(f2bf2(v.x, v.y), f2bf2(v.z, v.w));
        *(uint2*)(d + i * 4) = o;
    }
}

// ---------------- 1) fused depthwise convs (3x3,5x5,7x7) -> bf16 cat ----------------
__global__ void dwconv3_kernel(const float* __restrict__ X,
                               const float* __restrict__ w1, const float* __restrict__ b1,
                               const float* __restrict__ w2, const float* __restrict__ b2,
                               const float* __restrict__ w3, const float* __restrict__ b3) {
    __shared__ float sx[38][39];
    __shared__ float swt[83];
    int c = blockIdx.y, b = blockIdx.z;
    int tile = blockIdx.x;
    int ty0 = (tile >> 2) * 32, tx0 = (tile & 3) * 32;
    const float* Xp = X + ((size_t)b * NC + c) * NHW;
    int tid = threadIdx.x;

    if (tid < 9)       swt[tid] = w1[c * 9 + tid];
    else if (tid < 34) swt[tid] = w2[c * 25 + (tid - 9)];
    else if (tid < 83) swt[tid] = w3[c * 49 + (tid - 34)];

    for (int i = tid; i < 38 * 38; i += 256) {
        int iy = i / 38, ix = i - iy * 38;
        int gy = ty0 + iy - 3, gx = tx0 + ix - 3;
        float v = 0.0f;
        if (gy >= 0 && gy < 128 && gx >= 0 && gx < 128) v = Xp[gy * 128 + gx];
        sx[iy][ix] = v;
    }
    __syncthreads();

    float bb1 = b1[c], bb2 = b2[c], bb3 = b3[c];
    size_t ob1 = ((size_t)b * 768 + c) * NHW;
    size_t ob2 = ((size_t)b * 768 + 256 + c) * NHW;
    size_t ob3 = ((size_t)b * 768 + 512 + c) * NHW;

    #pragma unroll
    for (int sub = 0; sub < 4; sub++) {
        int oy = (tid >> 5) + sub * 8;
        int ox = (tid & 31);
        int cy = oy + 3, cx = ox + 3;
        float a1 = bb1, a2 = bb2, a3 = bb3;
        #pragma unroll
        for (int dy = -3; dy <= 3; dy++) {
            #pragma unroll
            for (int dx = -3; dx <= 3; dx++) {
                float v = sx[cy + dy][cx + dx];
                a3 += v * swt[34 + (dy + 3) * 7 + (dx + 3)];
                if (dy >= -2 && dy <= 2 && dx >= -2 && dx <= 2)
                    a2 += v * swt[9 + (dy + 2) * 5 + (dx + 2)];
                if (dy >= -1 && dy <= 1 && dx >= -1 && dx <= 1)
                    a1 += v * swt[(dy + 1) * 3 + (dx + 1)];
            }
        }
        int po = (ty0 + oy) * 128 + tx0 + ox;
        g_cat[ob1 + po] = __float2bfloat16_rn(a1);
        g_cat[ob2 + po] = __float2bfloat16_rn(a2);
        g_cat[ob3 + po] = __float2bfloat16_rn(a3);
    }
}

// ---------------- cat [b][k][p] -> cat_t [b*NHW+p][k] (bf16 transpose) ----------------
__global__ void cat_transpose(const bf16* __restrict__ S, bf16* __restrict__ D) {
    __shared__ bf16 sm[64][66];
    int p0 = blockIdx.x * 64, k0 = blockIdx.y * 64, b = blockIdx.z;
    int tid = threadIdx.x;
    {
        int k = tid >> 2;
        int pc = (tid & 3) * 16;
        const bf16* src = S + ((size_t)(b * 768 + k0 + k)) * NHW + p0 + pc;
        uint4 v0 = *(const uint4*)src;
        uint4 v1 = *(const uint4*)(src + 8);
        uint32_t* dst = (uint32_t*)&sm[k][pc];
        dst[0] = v0.x; dst[1] = v0.y; dst[2] = v0.z; dst[3] = v0.w;
        dst[4] = v1.x; dst[5] = v1.y; dst[6] = v1.z; dst[7] = v1.w;
    }
    __syncthreads();
    {
        int p = tid >> 2;
        int kc = (tid & 3) * 16;
        uint32_t w[8];
        #pragma unroll
        for (int j = 0; j < 8; j++) {
            bf16 lo = sm[kc + 2 * j][p];
            bf16 hi = sm[kc + 2 * j + 1][p];
            __nv_bfloat162 h2 = __halves2bfloat162(lo, hi);
            w[j] = *reinterpret_cast<uint32_t*>(&h2);
        }
        bf16* dst = D + ((size_t)(b * NHW + p0 + p)) * 768 + k0 + kc;
        *(uint4*)dst = make_uint4(w[0], w[1], w[2], w[3]);
        *(uint4*)(dst + 8) = make_uint4(w[4], w[5], w[6], w[7]);
    }
}

// ---------------- transpose x [B,C,HW] -> token-major fp32 ----------------
__global__ void to_tok(const float* __restrict__ X, float* __restrict__ T) {
    __shared__ float sm[64][65];
    int p0 = blockIdx.x * 64, c0 = blockIdx.y * 64, b = blockIdx.z;
    int tid = threadIdx.x;
    #pragma unroll
    for (int it = 0; it < 4; it++) {
        int c = it * 16 + (tid >> 4);
        int p4 = (tid & 15) * 4;
        float4 v = *(const float4*)&X[((size_t)(b * NC + c0 + c)) * NHW + p0 + p4];
        sm[c][p4 + 0] = v.x; sm[c][p4 + 1] = v.y; sm[c][p4 + 2] = v.z; sm[c][p4 + 3] = v.w;
    }
    __syncthreads();
    #pragma unroll
    for (int it = 0; it < 4; it++) {
        int p = it * 16 + (tid >> 4);
        int c4 = (tid & 15) * 4;
        float4 v = make_float4(sm[c4][p], sm[c4 + 1][p], sm[c4 + 2][p], sm[c4 + 3][p]);
        *(float4*)&T[((size_t)(b * NHW + p0 + p)) * NC + c0 + c4] = v;
    }
}

// ---------------- final: out[b,c,p] = R[t][c] + P[t][c], transposed ----------------
__global__ void from_tok_add(const float* __restrict__ R, const float* __restrict__ P,
                             float* __restrict__ O) {
    __shared__ float sm[64][65];
    int p0 = blockIdx.x * 64, c0 = blockIdx.y * 64, b = blockIdx.z;
    int tid = threadIdx.x;
    #pragma unroll
    for (int it = 0; it < 4; it++) {
        int p = it * 16 + (tid >> 4);
        int c4 = (tid & 15) * 4;
        size_t row = ((size_t)(b * NHW + p0 + p)) * NC + c0 + c4;
        float4 a = *(const float4*)&R[row];
        float4 q = *(const float4*)&P[row];
        sm[c4 + 0][p] = a.x + q.x; sm[c4 + 1][p] = a.y + q.y;
        sm[c4 + 2][p] = a.z + q.z; sm[c4 + 3][p] = a.w + q.w;
    }
    __syncthreads();
    #pragma unroll
    for (int it = 0; it < 4; it++) {
        int c = it * 16 + (tid >> 4);
        int p4 = (tid & 15) * 4;
        float4 v = make_float4(sm[c][p4], sm[c][p4 + 1], sm[c][p4 + 2], sm[c][p4 + 3]);
        *(float4*)&O[((size_t)(b * NC + c0 + c)) * NHW + p0 + p4] = v;
    }
}

// ---------------- fused LN + permute -> bf16 tokens ----------------
__global__ void ln_perm(const float* __restrict__ R, const float* __restrict__ gam,
                        const float* __restrict__ bet, bf16* __restrict__ T, int mode) {
    int warp = threadIdx.x >> 5, lane = threadIdx.x & 31;
    int t = blockIdx.x * 8 + warp;
    int b = t >> 14, r = t & 16383;
    int p;
    if (mode == 2) p = r;
    else {
        int win = r >> 6, pos = r & 63;
        int wy = win >> 4, wx = win & 15;
        int py = pos >> 3, px = pos & 7;
        if (mode == 0) p = (wy * 8 + py) * 128 + wx * 8 + px;
        else           p = (py * 16 + wy) * 128 + px * 16 + wx;
    }
    const float* src = R + ((size_t)b * NHW + p) * NC;
    float4 v0 = *(const float4*)(src + lane * 4);
    float4 v1 = *(const float4*)(src + 128 + lane * 4);
    float s  = v0.x + v0.y + v0.z + v0.w + v1.x + v1.y + v1.z + v1.w;
    float s2 = v0.x * v0.x + v0.y * v0.y + v0.z * v0.z + v0.w * v0.w
             + v1.x * v1.x + v1.y * v1.y + v1.z * v1.z + v1.w * v1.w;
    #pragma unroll
    for (int o = 16; o; o >>= 1) {
        s  += __shfl_xor_sync(0xffffffff, s, o);
        s2 += __shfl_xor_sync(0xffffffff, s2, o);
    }
    float m = s * (1.0f / NC);
    float rs = rsqrtf(s2 * (1.0f / NC) - m * m + 1e-5f);
    float4 g0 = *(const float4*)(gam + lane * 4);
    float4 g1 = *(const float4*)(gam + 128 + lane * 4);
    float4 b0 = *(const float4*)(bet + lane * 4);
    float4 b1 = *(const float4*)(bet + 128 + lane * 4);
    bf16* dst = T + (size_t)t * NC;
    float o0x = (v0.x - m) * rs * g0.x + b0.x, o0y = (v0.y - m) * rs * g0.y + b0.y;
    float o0z = (v0.z - m) * rs * g0.z + b0.z, o0w = (v0.w - m) * rs * g0.w + b0.w;
    float o1x = (v1.x - m) * rs * g1.x + b1.x, o1y = (v1.y - m) * rs * g1.y + b1.y;
    float o1z = (v1.z - m) * rs * g1.z + b1.z, o1w = (v1.w - m) * rs * g1.w + b1.w;
    *(uint2*)(dst + lane * 4)       = make_uint2(f2bf2(o0x, o0y), f2bf2(o0z, o0w));
    *(uint2*)(dst + 128 + lane * 4) = make_uint2(f2bf2(o1x, o1y), f2bf2(o1z, o1w));
}

// ---------------- residual add with permuted proj rows (fp32) ----------------
__global__ void resadd_perm(const float* __restrict__ base, const float* __restrict__ P,
                            float* __restrict__ Rout, int mode) {
    int warp = threadIdx.x >> 5, lane = threadIdx.x & 31;
    int t = blockIdx.x * 8 + warp;
    int b = t >> 14, p = t & 16383;
    int h = p >> 7, w = p & 127;
    int tp;
    if (mode == 2) tp = t;
    else if (mode == 0) {
        int win = (h >> 3) * 16 + (w >> 3);
        int pos = (h & 7) * 8 + (w & 7);
        tp = (b << 14) + win * 64 + pos;
    } else {
        int K2 = h >> 3, K1 = ((h & 7) << 1) | (w >> 6);
        int S1 = (w >> 3) & 7, S2 = w & 7;
        tp = (b << 14) + (K1 * 16 + K2) * 64 + S1 * 8 + S2;
    }
    const float* pb = base + (size_t)t * NC;
    const float* pp = P + (size_t)tp * NC;
    float* po = Rout + (size_t)t * NC;
    float4 a0 = *(const float4*)(pb + lane * 4);
    float4 a1 = *(const float4*)(pb + 128 + lane * 4);
    float4 q0 = *(const float4*)(pp + lane * 4);
    float4 q1 = *(const float4*)(pp + 128 + lane * 4);
    a0.x += q0.x; a0.y += q0.y; a0.z += q0.z; a0.w += q0.w;
    a1.x += q1.x; a1.y += q1.y; a1.z += q1.z; a1.w += q1.w;
    *(float4*)(po + lane * 4) = a0;
    *(float4*)(po + 128 + lane * 4) = a1;
}

// ================= bf16 tensor-core NT GEMM, 128x128 tile =================
// C[M,N] = A[M,K] * B[N,K]^T + bias[n]; BK=64, 8 warps (2 wm x 4 wn),
// warp tile 64x32. SMEM row = 64 bf16 in 4 chunks of 8 u32; chunk c at
// physical (c ^ ((row>>2)&3)); words interleave pairs (j, j+4). Row stride 40.
template<typename OutT, bool GELU>
__global__ __launch_bounds__(256, 1) void gemm_bf16_nt(
        const bf16* __restrict__ A, const bf16* __restrict__ B,
        const float* __restrict__ bias, OutT* __restrict__ C, int N, int K) {
    __shared__ uint32_t As[128 * 40];
    __shared__ uint32_t Bs[128 * 40];
    const int tid = threadIdx.x;
    const int lane = tid & 31, warp = tid >> 5;
    const int wm = warp >> 2, wn = warp & 3;
    const int g = lane >> 2, q = lane & 3;
    const size_t m0 = (size_t)blockIdx.y * 128;
    const int n0 = blockIdx.x * 128;

    const int ar = tid >> 1;          // 0..127 (row for both A and B tiles)
    const int ach = (tid & 1) * 2;    // chunks {0,1} or {2,3}
    const bf16* Ag = A + (m0 + ar) * K + ach * 16;
    const bf16* Bg = B + (size_t)(n0 + ar) * K + ach * 16;
    const int asw = (ar >> 2) & 3;
    uint32_t* Asr = As + ar * 40;
    uint32_t* Bsr = Bs + ar * 40;

    float acc[4][4][4];
    #pragma unroll
    for (int i = 0; i < 4; i++)
        #pragma unroll
        for (int j = 0; j < 4; j++)
            #pragma unroll
            for (int k = 0; k < 4; k++) acc[i][j][k] = 0.0f;

    uint4 aR[4], bR[4];
    #pragma unroll
    for (int c = 0; c < 2; c++) {
        aR[2 * c]     = *(const uint4*)(Ag + c * 16);
        aR[2 * c + 1] = *(const uint4*)(Ag + c * 16 + 8);
        bR[2 * c]     = *(const uint4*)(Bg + c * 16);
        bR[2 * c + 1] = *(const uint4*)(Bg + c * 16 + 8);
    }

    for (int k0 = 0; k0 < K; k0 += 64) {
        #pragma unroll
        for (int c = 0; c < 2; c++) {
            uint4 lo = aR[2 * c], hi = aR[2 * c + 1];
            uint2* dst = (uint2*)(Asr + ((ach + c) ^ asw) * 8);
            dst[0] = make_uint2(lo.x, hi.x);
            dst[1] = make_uint2(lo.y, hi.y);
            dst[2] = make_uint2(lo.z, hi.z);
            dst[3] = make_uint2(lo.w, hi.w);
            lo = bR[2 * c]; hi = bR[2 * c + 1];
            dst = (uint2*)(Bsr + ((ach + c) ^ asw) * 8);
            dst[0] = make_uint2(lo.x, hi.x);
            dst[1] = make_uint2(lo.y, hi.y);
            dst[2] = make_uint2(lo.z, hi.z);
            dst[3] = make_uint2(lo.w, hi.w);
        }
        __syncthreads();
        if (k0 + 64 < K) {
            #pragma unroll
            for (int c = 0; c < 2; c++) {
                aR[2 * c]     = *(const uint4*)(Ag + k0 + 64 + c * 16);
                aR[2 * c + 1] = *(const uint4*)(Ag + k0 + 64 + c * 16 + 8);
                bR[2 * c]     = *(const uint4*)(Bg + k0 + 64 + c * 16);
                bR[2 * c + 1] = *(const uint4*)(Bg + k0 + 64 + c * 16 + 8);
            }
        }
        #pragma unroll
        for (int kc = 0; kc < 4; kc++) {
            uint32_t afr[4][4], bfr[4][2];
            #pragma unroll
            for (int mt = 0; mt < 4; mt++) {
                int r0 = wm * 64 + mt * 16 + g;
                int r1 = r0 + 8;
                uint2 lo = *(uint2*)&As[r0 * 40 + ((kc ^ ((r0 >> 2) & 3)) * 8) + 2 * q];
                uint2 hi = *(uint2*)&As[r1 * 40 + ((kc ^ ((r1 >> 2) & 3)) * 8) + 2 * q];
                afr[mt][0] = lo.x; afr[mt][1] = hi.x; afr[mt][2] = lo.y; afr[mt][3] = hi.y;
            }
            #pragma unroll
            for (int nt = 0; nt < 4; nt++) {
                int rn = wn * 32 + nt * 8 + g;
                uint2 bb = *(uint2*)&Bs[rn * 40 + ((kc ^ ((rn >> 2) & 3)) * 8) + 2 * q];
                bfr[nt][0] = bb.x; bfr[nt][1] = bb.y;
            }
            #pragma unroll
            for (int mt = 0; mt < 4; mt++)
                #pragma unroll
                for (int nt = 0; nt < 4; nt++)
                    mma_bf16(acc[mt][nt], afr[mt], bfr[nt]);
        }
        __syncthreads();
    }

    #pragma unroll
    for (int mt = 0; mt < 4; mt++) {
        size_t rg = m0 + wm * 64 + mt * 16 + g;
        #pragma unroll
        for (int nt = 0; nt < 4; nt++) {
            int cb = n0 + wn * 32 + nt * 8 + 2 * q;
            float b0 = bias[cb], b1 = bias[cb + 1];
            float v0 = acc[mt][nt][0] + b0, v1 = acc[mt][nt][1] + b1;
            float v2 = acc[mt][nt][2] + b0, v3 = acc[mt][nt][3] + b1;
            if (GELU) {
                v0 = gelu_exact(v0); v1 = gelu_exact(v1);
                v2 = gelu_exact(v2); v3 = gelu_exact(v3);
            }
            if constexpr (sizeof(OutT) == 4) {
                *(float2*)&((float*)C)[rg * N + cb] = make_float2(v0, v1);
                *(float2*)&((float*)C)[(rg + 8) * N + cb] = make_float2(v2, v3);
            } else {
                *(uint32_t*)&((bf16*)C)[rg * N + cb] = f2bf2(v0, v1);
                *(uint32_t*)&((bf16*)C)[(rg + 8) * N + cb] = f2bf2(v2, v3);
            }
        }
    }
}

// ================= tensor-core attention, L=64, D=32 =================
// Block = (window, head); 128 thr = 4 warps; warp w owns query rows [16w,16w+16).
// S = Q K^T via mma (fp32 acc), softmax fully in registers, P packed from the
// accumulator directly into AV A-fragments (no smem roundtrip), AV = P V via mma.
// Q/K smem: 64 rows x 32 bf16, 2 chunks/row, stride 24 u32, chunk swizzle c^((r>>2)&1).
// V^T smem: 32 rows(d) x 64(j) bf16, GEMM format (4 chunks, stride 40, c^((r>>2)&3)).
__global__ void attn_kernel(const bf16* __restrict__ QKV, bf16* __restrict__ O) {
    __shared__ uint32_t sq[64 * 24];
    __shared__ uint32_t sk[64 * 24];
    __shared__ uint32_t sv[32 * 40];
    int wh = blockIdx.x;
    int win = wh >> 3, head = wh & 7;
    int tid = threadIdx.x;
    int warp = tid >> 5, lane = tid & 31;
    int g = lane >> 2, q = lane & 3;
    const bf16* base = QKV + (size_t)win * 64 * 768 + head * 32;

    // load Q,K (row = t>>1, chunk = t&1)
    {
        int r = tid >> 1, ch = tid & 1;
        int sw = ch ^ ((r >> 2) & 1);
        const bf16* src = base + (size_t)r * 768 + ch * 16;
        uint4 lo = *(const uint4*)src;
        uint4 hi = *(const uint4*)(src + 8);
        uint2* dst = (uint2*)(sq + r * 24 + sw * 8);
        dst[0] = make_uint2(lo.x, hi.x); dst[1] = make_uint2(lo.y, hi.y);
        dst[2] = make_uint2(lo.z, hi.z); dst[3] = make_uint2(lo.w, hi.w);
        lo = *(const uint4*)(src + 256);
        hi = *(const uint4*)(src + 264);
        dst = (uint2*)(sk + r * 24 + sw * 8);
        dst[0] = make_uint2(lo.x, hi.x); dst[1] = make_uint2(lo.y, hi.y);
        dst[2] = make_uint2(lo.z, hi.z); dst[3] = make_uint2(lo.w, hi.w);
    }
    // load V transposed: thread t -> j-pair jp = t>>2, d-group d0 = (t&3)*8
    {
        int jp = tid >> 2, d0 = (tid & 3) * 8;
        int j = jp * 2;
        const bf16* v0p = base + (size_t)j * 768 + 512 + d0;
        uint4 v0 = *(const uint4*)v0p;
        uint4 v1 = *(const uint4*)(v0p + 768);
        uint32_t u0[4] = {v0.x, v0.y, v0.z, v0.w};
        uint32_t u1[4] = {v1.x, v1.y, v1.z, v1.w};
        int cj = jp >> 3;                    // j chunk
        int pr = jp & 7;                     // pair index within chunk
        int wp = ((pr & 3) << 1) | (pr >> 2);
        #pragma unroll
        for (int m = 0; m < 4; m++) {
            int d = d0 + 2 * m;
            uint32_t loP = (u0[m] & 0xffffu) | (u1[m] << 16);
            uint32_t hiP = (u0[m] >> 16) | (u1[m] & 0xffff0000u);
            sv[d * 40 + ((cj ^ ((d >> 2) & 3)) * 8) + wp] = loP;
            sv[(d + 1) * 40 + ((cj ^ (((d + 1) >> 2) & 3)) * 8) + wp] = hiP;
        }
    }
    __syncthreads();

    // S = Q K^T : warp w rows [16w, 16w+16), full 64 cols (nt 0..7)
    float sacc[8][4];
    #pragma unroll
    for (int nt = 0; nt < 8; nt++)
        #pragma unroll
        for (int i = 0; i < 4; i++) sacc[nt][i] = 0.0f;
    #pragma unroll
    for (int kc = 0; kc < 2; kc++) {
        int r0 = warp * 16 + g, r1 = r0 + 8;
        uint2 lo = *(uint2*)&sq[r0 * 24 + ((kc ^ ((r0 >> 2) & 1)) * 8) + 2 * q];
        uint2 hi = *(uint2*)&sq[r1 * 24 + ((kc ^ ((r1 >> 2) & 1)) * 8) + 2 * q];
        uint32_t a[4] = {lo.x, hi.x, lo.y, hi.y};
        #pragma unroll
        for (int nt = 0; nt < 8; nt++) {
            int rn = nt * 8 + g;
            uint2 bb = *(uint2*)&sk[rn * 24 + ((kc ^ ((rn >> 2) & 1)) * 8) + 2 * q];
            uint32_t bf[2] = {bb.x, bb.y};
            mma_bf16(sacc[nt], a, bf);
        }
    }

    // softmax (rows g -> [0],[1]; rows g+8 -> [2],[3]); reduce across quad lanes
    const float scale = 0.17677669529663687f;
    #pragma unroll
    for (int nt = 0; nt < 8; nt++)
        #pragma unroll
        for (int i = 0; i < 4; i++) sacc[nt][i] *= scale;
    float mx0 = -1e30f, mx1 = -1e30f;
    #pragma unroll
    for (int nt = 0; nt < 8; nt++) {
        mx0 = fmaxf(mx0, fmaxf(sacc[nt][0], sacc[nt][1]));
        mx1 = fmaxf(mx1, fmaxf(sacc[nt][2], sacc[nt][3]));
    }
    mx0 = fmaxf(mx0, __shfl_xor_sync(0xffffffff, mx0, 1));
    mx0 = fmaxf(mx0, __shfl_xor_sync(0xffffffff, mx0, 2));
    mx1 = fmaxf(mx1, __shfl_xor_sync(0xffffffff, mx1, 1));
    mx1 = fmaxf(mx1, __shfl_xor_sync(0xffffffff, mx1, 2));
    float sum0 = 0.0f, sum1 = 0.0f;
    #pragma unroll
    for (int nt = 0; nt < 8; nt++) {
        sacc[nt][0] = __expf(sacc[nt][0] - mx0);
        sacc[nt][1] = __expf(sacc[nt][1] - mx0);
        sacc[nt][2] = __expf(sacc[nt][2] - mx1);
        sacc[nt][3] = __expf(sacc[nt][3] - mx1);
        sum0 += sacc[nt][0] + sacc[nt][1];
        sum1 += sacc[nt][2] + sacc[nt][3];
    }
    sum0 += __shfl_xor_sync(0xffffffff, sum0, 1);
    sum0 += __shfl_xor_sync(0xffffffff, sum0, 2);
    sum1 += __shfl_xor_sync(0xffffffff, sum1, 1);
    sum1 += __shfl_xor_sync(0xffffffff, sum1, 2);
    float inv0 = 1.0f / sum0, inv1 = 1.0f / sum1;
    #pragma unroll
    for (int nt = 0; nt < 8; nt++) {
        sacc[nt][0] *= inv0; sacc[nt][1] *= inv0;
        sacc[nt][2] *= inv1; sacc[nt][3] *= inv1;
    }

    // O = P V : A-frags packed straight from sacc; B = V^T smem
    float oacc[4][4];
    #pragma unroll
    for (int nt = 0; nt < 4; nt++)
        #pragma unroll
        for (int i = 0; i < 4; i++) oacc[nt][i] = 0.0f;
    #pragma unroll
    for (int kc = 0; kc < 4; kc++) {
        uint32_t a[4];
        a[0] = f2bf2(sacc[2 * kc][0], sacc[2 * kc][1]);
        a[1] = f2bf2(sacc[2 * kc][2], sacc[2 * kc][3]);
        a[2] = f2bf2(sacc[2 * kc + 1][0], sacc[2 * kc + 1][1]);
        a[3] = f2bf2(sacc[2 * kc + 1][2], sacc[2 * kc + 1][3]);
        #pragma unroll
        for (int nt = 0; nt < 4; nt++) {
            int rn = nt * 8 + g;
            uint2 bb = *(uint2*)&sv[rn * 40 + ((kc ^ ((rn >> 2) & 3)) * 8) + 2 * q];
            uint32_t bf[2] = {bb.x, bb.y};
            mma_bf16(oacc[nt], a, bf);
        }
    }

    // write O (bf16 pairs)
    int row0 = win * 64 + warp * 16 + g;
    bf16* o0 = O + (size_t)row0 * NC + head * 32;
    bf16* o1 = o0 + 8 * NC;
    #pragma unroll
    for (int nt = 0; nt < 4; nt++) {
        int cb = nt * 8 + 2 * q;
        *(uint32_t*)&o0[cb] = f2bf2(oacc[nt][0], oacc[nt][1]);
        *(uint32_t*)&o1[cb] = f2bf2(oacc[nt][2], oacc[nt][3]);
    }
}

// ---------------- launch ----------------
extern "C" void kernel_launch(void* const* d_in, const int* in_sizes, int n_in,
                              void* d_out, int out_size) {
    const float* x      = (const float*)d_in[0];
    const float* w1     = (const float*)d_in[1];
    const float* b1     = (const float*)d_in[2];
    const float* w2     = (const float*)d_in[3];
    const float* b2     = (const float*)d_in[4];
    const float* w3     = (const float*)d_in[5];
    const float* b3     = (const float*)d_in[6];
    const float* wf     = (const float*)d_in[7];
    const float* bf     = (const float*)d_in[8];
    const float* gw     = (const float*)d_in[9];
    const float* bw     = (const float*)d_in[10];
    const float* wqkv_w = (const float*)d_in[11];
    const float* bqkv_w = (const float*)d_in[12];
    const float* wo_w   = (const float*)d_in[13];
    const float* bo_w   = (const float*)d_in[14];
    const float* gg     = (const float*)d_in[15];
    const float* bg     = (const float*)d_in[16];
    const float* wqkv_g = (const float*)d_in[17];
    const float* bqkv_g = (const float*)d_in[18];
    const float* wo_g   = (const float*)d_in[19];
    const float* bo_g   = (const float*)d_in[20];
    const float* gm     = (const float*)d_in[21];
    const float* bm     = (const float*)d_in[22];
    const float* m1w    = (const float*)d_in[23];
    const float* m1b    = (const float*)d_in[24];
    const float* m2w    = (const float*)d_in[25];
    const float* m2b    = (const float*)d_in[26];
    float* out = (float*)d_out;

    void *p_cat, *p_catt, *p_xm, *p_xtok, *p_tok, *p_qkv, *p_att, *p_proj, *p_h1, *p_wb;
    cudaGetSymbolAddress(&p_cat, g_cat);
    cudaGetSymbolAddress(&p_catt, g_catt);
    cudaGetSymbolAddress(&p_xm, g_xm);
    cudaGetSymbolAddress(&p_xtok, g_xtok);
    cudaGetSymbolAddress(&p_tok, g_tok);
    cudaGetSymbolAddress(&p_qkv, g_qkv);
    cudaGetSymbolAddress(&p_att, g_att);
    cudaGetSymbolAddress(&p_proj, g_proj);
    cudaGetSymbolAddress(&p_h1, g_h1);
    cudaGetSymbolAddress(&p_wb, g_wb);
    bf16* cat  = (bf16*)p_cat;    bf16* catt = (bf16*)p_catt;
    float* xm  = (float*)p_xm;    float* xtok = (float*)p_xtok;
    bf16* tok  = (bf16*)p_tok;    bf16* qkv  = (bf16*)p_qkv;
    bf16* att  = (bf16*)p_att;    float* proj = (float*)p_proj;
    bf16* h1   = (bf16*)p_h1;     bf16* wb   = (bf16*)p_wb;

    // weight conversions (bf16)
    cvt_w<<<192, 256>>>(wf,     wb + OFF_WF,   49152);
    cvt_w<<<192, 256>>>(wqkv_w, wb + OFF_QKVW, 49152);
    cvt_w<<<192, 256>>>(wqkv_g, wb + OFF_QKVG, 49152);
    cvt_w<<<64,  256>>>(wo_w,   wb + OFF_WOW,  16384);
    cvt_w<<<64,  256>>>(wo_g,   wb + OFF_WOG,  16384);
    cvt_w<<<256, 256>>>(m1w,    wb + OFF_M1,   65536);
    cvt_w<<<256, 256>>>(m2w,    wb + OFF_M2,   65536);

    // depthwise convs -> cat (bf16); transpose to token-major; x -> token-major
    dwconv3_kernel<<<dim3(16, NC, NB), 256>>>(x, w1, b1, w2, b2, w3, b3);
    cat_transpose<<<dim3(256, 12, NB), 256>>>(cat, catt);
    to_tok<<<dim3(256, 4, NB), 256>>>(x, xtok);

    // 1x1 fuse as NT GEMM -> xm (fp32, token-major)
    gemm_bf16_nt<float, false><<<dim3(2, 1024), 256>>>(catt, wb + OFF_WF, bf, xm, 256, 768);

    // ---- window branch ----
    ln_perm<<<16384, 256>>>(xm, gw, bw, tok, 0);
    gemm_bf16_nt<bf16, false><<<dim3(6, 1024), 256>>>(tok, wb + OFF_QKVW, bqkv_w, qkv, 768, 256);
    attn_kernel<<<16384, 128>>>(qkv, att);
    gemm_bf16_nt<float, false><<<dim3(2, 1024), 256>>>(att, wb + OFF_WOW, bo_w, proj, 256, 256);
    resadd_perm<<<16384, 256>>>(xtok, proj, xm, 0);

    // ---- grid branch ----
    ln_perm<<<16384, 256>>>(xm, gg, bg, tok, 1);
    gemm_bf16_nt<bf16, false><<<dim3(6, 1024), 256>>>(tok, wb + OFF_QKVG, bqkv_g, qkv, 768, 256);
    attn_kernel<<<16384, 128>>>(qkv, att);
    gemm_bf16_nt<float, false><<<dim3(2, 1024), 256>>>(att, wb + OFF_WOG, bo_g, proj, 256, 256);
    resadd_perm<<<16384, 256>>>(xm, proj, xm, 1);

    // ---- MLP ----
    ln_perm<<<16384, 256>>>(xm, gm, bm, tok, 2);
    gemm_bf16_nt<bf16, true ><<<dim3(8, 1024), 256>>>(tok, wb + OFF_M1, m1b, h1, 1024, 256);
    gemm_bf16_nt<float, false><<<dim3(2, 1024), 256>>>(h1, wb + OFF_M2, m2b, proj, 256, 1024);
    from_tok_add<<<dim3(256, 4, NB), 256>>>(xm, proj, out);
}

// round 7
// speedup vs baseline: 5.0497x; 1.2441x over previous
#include <cuda_runtime.h>
#include <cuda_bf16.h>
#include <math.h>
#include <stdint.h>

// ---------------- problem constants ----------------
#define NB   8
#define NC   256
#define NHW  16384     // 128*128
#define NTOK 131072    // NB*NHW

typedef __nv_bfloat16 bf16;

// ---------------- scratch (device globals) ----------------
__device__ bf16  g_cat [(size_t)NB * 768 * NHW];   // [B,3C,HW] bf16
__device__ bf16  g_catt[(size_t)NTOK * 768];       // cat token-major bf16
__device__ float g_xm  [(size_t)NTOK * NC];        // residual stream (fp32)
__device__ float g_xtok[(size_t)NTOK * NC];        // x token-major (fp32)
__device__ bf16  g_tok [(size_t)NTOK * NC];        // LN'd tokens bf16
__device__ bf16  g_qkv [(size_t)NTOK * 768];
__device__ bf16  g_att [(size_t)NTOK * NC];
__device__ float g_proj[(size_t)NTOK * NC];
__device__ bf16  g_h1  [(size_t)NTOK * 1024];
__device__ bf16  g_wb  [1245184];                  // all weights converted to bf16

// weight offsets in g_wb (elements)
#define OFF_WF   0
#define OFF_QKVW 196608
#define OFF_QKVG 393216
#define OFF_WOW  589824
#define OFF_WOG  655360
#define OFF_M1   720896
#define OFF_M2   983040

// ---------------- helpers ----------------
__device__ __forceinline__ float gelu_exact(float x) {
    return 0.5f * x * (1.0f + erff(x * 0.70710678118654752f));
}
__device__ __forceinline__ uint32_t f2bf2(float a, float b) {
    __nv_bfloat162 h = __floats2bfloat162_rn(a, b);
    return *reinterpret_cast<uint32_t*>(&h);
}
__device__ __forceinline__ void mma_bf16(float* d, const uint32_t* a, const uint32_t* b) {
    asm volatile(
        "mma.sync.aligned.m16n8k16.row.col.f32.bf16.bf16.f32 "
        "{%0,%1,%2,%3}, {%4,%5,%6,%7}, {%8,%9}, {%0,%1,%2,%3};"
        : "+f"(d[0]), "+f"(d[1]), "+f"(d[2]), "+f"(d[3])
        : "r"(a[0]), "r"(a[1]), "r"(a[2]), "r"(a[3]), "r"(b[0]), "r"(b[1]));
}
__device__ __forceinline__ uint32_t smem_u32(const void* p) {
    return (uint32_t)__cvta_generic_to_shared(p);
}
__device__ __forceinline__ void cp_async16(uint32_t s, const void* gp) {
    asm volatile("cp.async.cg.shared.global [%0], [%1], 16;" :: "r"(s), "l"(gp));
}
__device__ __forceinline__ void cp_commit() {
    asm volatile("cp.async.commit_group;");
}
template<int W> __device__ __forceinline__ void cp_wait() {
    asm volatile("cp.async.wait_group %0;" :: "n"(W));
}
__device__ __forceinline__ void ldsm_x4(uint32_t& a, uint32_t& b, uint32_t& c, uint32_t& d,
                                        uint32_t addr) {
    asm volatile("ldmatrix.sync.aligned.m8n8.x4.shared.b16 {%0,%1,%2,%3}, [%4];"
        : "=r"(a), "=r"(b), "=r"(c), "=r"(d) : "r"(addr));
}

// ---------------- merged weight fp32 -> bf16 ----------------
__global__ void cvt_all(const float* __restrict__ wf, const float* __restrict__ qw,
                        const float* __restrict__ qg, const float* __restrict__ ow,
                        const float* __restrict__ og, const float* __restrict__ m1,
                        const float* __restrict__ m2, bf16* __restrict__ d) {
    int i = blockIdx.x * 256 + threadIdx.x;   // quad index
    if (i >= 311296) return;
    const float* src;
    int local;
    if (i < 49152)        { src = wf; local = i; }
    else if (i < 98304)   { src = qw; local = i - 49152; }
    else if (i < 147456)  { src = qg; local = i - 98304; }
    else if (i < 163840)  { src = ow; local = i - 147456; }
    else if (i < 180224)  { src = og; local = i - 163840; }
    else if (i < 245760)  { src = m1; local = i - 180224; }
    else                  { src = m2; local = i - 245760; }
    float4 v = *(const float4*)(src + (size_t)local * 4);
    *(uint2*)(d + (size_t)i * 4) = make_uint2(f2bf2(v.x, v.y), f2bf2(v.z, v.w));
}

// ---------------- 1) fused depthwise convs (3x3,5x5,7x7) -> bf16 cat ----------------
__global__ void dwconv3_kernel(const float* __restrict__ X,
                               const float* __restrict__ w1, const float* __restrict__ b1,
                               const float* __restrict__ w2, const float* __restrict__ b2,
                               const float* __restrict__ w3, const float* __restrict__ b3) {
    __shared__ float sx[38][39];
    __shared__ float swt[83];
    int c = blockIdx.y, b = blockIdx.z;
    int tile = blockIdx.x;
    int ty0 = (tile >> 2) * 32, tx0 = (tile & 3) * 32;
    const float* Xp = X + ((size_t)b * NC + c) * NHW;
    int tid = threadIdx.x;

    if (tid < 9)       swt[tid] = w1[c * 9 + tid];
    else if (tid < 34) swt[tid] = w2[c * 25 + (tid - 9)];
    else if (tid < 83) swt[tid] = w3[c * 49 + (tid - 34)];

    for (int i = tid; i < 38 * 38; i += 256) {
        int iy = i / 38, ix = i - iy * 38;
        int gy = ty0 + iy - 3, gx = tx0 + ix - 3;
        float v = 0.0f;
        if (gy >= 0 && gy < 128 && gx >= 0 && gx < 128) v = Xp[gy * 128 + gx];
        sx[iy][ix] = v;
    }
    __syncthreads();

    float bb1 = b1[c], bb2 = b2[c], bb3 = b3[c];
    size_t ob1 = ((size_t)b * 768 + c) * NHW;
    size_t ob2 = ((size_t)b * 768 + 256 + c) * NHW;
    size_t ob3 = ((size_t)b * 768 + 512 + c) * NHW;

    #pragma unroll
    for (int sub = 0; sub < 4; sub++) {
        int oy = (tid >> 5) + sub * 8;
        int ox = (tid & 31);
        int cy = oy + 3, cx = ox + 3;
        float a1 = bb1, a2 = bb2, a3 = bb3;
        #pragma unroll
        for (int dy = -3; dy <= 3; dy++) {
            #pragma unroll
            for (int dx = -3; dx <= 3; dx++) {
                float v = sx[cy + dy][cx + dx];
                a3 += v * swt[34 + (dy + 3) * 7 + (dx + 3)];
                if (dy >= -2 && dy <= 2 && dx >= -2 && dx <= 2)
                    a2 += v * swt[9 + (dy + 2) * 5 + (dx + 2)];
                if (dy >= -1 && dy <= 1 && dx >= -1 && dx <= 1)
                    a1 += v * swt[(dy + 1) * 3 + (dx + 1)];
            }
        }
        int po = (ty0 + oy) * 128 + tx0 + ox;
        g_cat[ob1 + po] = __float2bfloat16_rn(a1);
        g_cat[ob2 + po] = __float2bfloat16_rn(a2);
        g_cat[ob3 + po] = __float2bfloat16_rn(a3);
    }
}

// ---------------- cat [b][k][p] -> cat_t [b*NHW+p][k] (bf16 transpose) ----------------
__global__ void cat_transpose(const bf16* __restrict__ S, bf16* __restrict__ D) {
    __shared__ bf16 sm[64][66];
    int p0 = blockIdx.x * 64, k0 = blockIdx.y * 64, b = blockIdx.z;
    int tid = threadIdx.x;
    {
        int k = tid >> 2;
        int pc = (tid & 3) * 16;
        const bf16* src = S + ((size_t)(b * 768 + k0 + k)) * NHW + p0 + pc;
        uint4 v0 = *(const uint4*)src;
        uint4 v1 = *(const uint4*)(src + 8);
        uint32_t* dst = (uint32_t*)&sm[k][pc];
        dst[0] = v0.x; dst[1] = v0.y; dst[2] = v0.z; dst[3] = v0.w;
        dst[4] = v1.x; dst[5] = v1.y; dst[6] = v1.z; dst[7] = v1.w;
    }
    __syncthreads();
    {
        int p = tid >> 2;
        int kc = (tid & 3) * 16;
        uint32_t w[8];
        #pragma unroll
        for (int j = 0; j < 8; j++) {
            bf16 lo = sm[kc + 2 * j][p];
            bf16 hi = sm[kc + 2 * j + 1][p];
            __nv_bfloat162 h2 = __halves2bfloat162(lo, hi);
            w[j] = *reinterpret_cast<uint32_t*>(&h2);
        }
        bf16* dst = D + ((size_t)(b * NHW + p0 + p)) * 768 + k0 + kc;
        *(uint4*)dst = make_uint4(w[0], w[1], w[2], w[3]);
        *(uint4*)(dst + 8) = make_uint4(w[4], w[5], w[6], w[7]);
    }
}

// ---------------- transpose x [B,C,HW] -> token-major fp32 ----------------
__global__ void to_tok(const float* __restrict__ X, float* __restrict__ T) {
    __shared__ float sm[64][65];
    int p0 = blockIdx.x * 64, c0 = blockIdx.y * 64, b = blockIdx.z;
    int tid = threadIdx.x;
    #pragma unroll
    for (int it = 0; it < 4; it++) {
        int c = it * 16 + (tid >> 4);
        int p4 = (tid & 15) * 4;
        float4 v = *(const float4*)&X[((size_t)(b * NC + c0 + c)) * NHW + p0 + p4];
        sm[c][p4 + 0] = v.x; sm[c][p4 + 1] = v.y; sm[c][p4 + 2] = v.z; sm[c][p4 + 3] = v.w;
    }
    __syncthreads();
    #pragma unroll
    for (int it = 0; it < 4; it++) {
        int p = it * 16 + (tid >> 4);
        int c4 = (tid & 15) * 4;
        float4 v = make_float4(sm[c4][p], sm[c4 + 1][p], sm[c4 + 2][p], sm[c4 + 3][p]);
        *(float4*)&T[((size_t)(b * NHW + p0 + p)) * NC + c0 + c4] = v;
    }
}

// ---------------- final: out[b,c,p] = R[t][c] + P[t][c], transposed ----------------
__global__ void from_tok_add(const float* __restrict__ R, const float* __restrict__ P,
                             float* __restrict__ O) {
    __shared__ float sm[64][65];
    int p0 = blockIdx.x * 64, c0 = blockIdx.y * 64, b = blockIdx.z;
    int tid = threadIdx.x;
    #pragma unroll
    for (int it = 0; it < 4; it++) {
        int p = it * 16 + (tid >> 4);
        int c4 = (tid & 15) * 4;
        size_t row = ((size_t)(b * NHW + p0 + p)) * NC + c0 + c4;
        float4 a = *(const float4*)&R[row];
        float4 q = *(const float4*)&P[row];
        sm[c4 + 0][p] = a.x + q.x; sm[c4 + 1][p] = a.y + q.y;
        sm[c4 + 2][p] = a.z + q.z; sm[c4 + 3][p] = a.w + q.w;
    }
    __syncthreads();
    #pragma unroll
    for (int it = 0; it < 4; it++) {
        int c = it * 16 + (tid >> 4);
        int p4 = (tid & 15) * 4;
        float4 v = make_float4(sm[c][p4], sm[c][p4 + 1], sm[c][p4 + 2], sm[c][p4 + 3]);
        *(float4*)&O[((size_t)(b * NC + c0 + c)) * NHW + p0 + p4] = v;
    }
}

// ---------------- fused LN + permute -> bf16 tokens (standalone, first LN) ----------------
__global__ void ln_perm(const float* __restrict__ R, const float* __restrict__ gam,
                        const float* __restrict__ bet, bf16* __restrict__ T, int mode) {
    int warp = threadIdx.x >> 5, lane = threadIdx.x & 31;
    int t = blockIdx.x * 8 + warp;
    int b = t >> 14, r = t & 16383;
    int p;
    if (mode == 2) p = r;
    else {
        int win = r >> 6, pos = r & 63;
        int wy = win >> 4, wx = win & 15;
        int py = pos >> 3, px = pos & 7;
        if (mode == 0) p = (wy * 8 + py) * 128 + wx * 8 + px;
        else           p = (py * 16 + wy) * 128 + px * 16 + wx;
    }
    const float* src = R + ((size_t)b * NHW + p) * NC;
    float4 v0 = *(const float4*)(src + lane * 4);
    float4 v1 = *(const float4*)(src + 128 + lane * 4);
    float s  = v0.x + v0.y + v0.z + v0.w + v1.x + v1.y + v1.z + v1.w;
    float s2 = v0.x * v0.x + v0.y * v0.y + v0.z * v0.z + v0.w * v0.w
             + v1.x * v1.x + v1.y * v1.y + v1.z * v1.z + v1.w * v1.w;
    #pragma unroll
    for (int o = 16; o; o >>= 1) {
        s  += __shfl_xor_sync(0xffffffff, s, o);
        s2 += __shfl_xor_sync(0xffffffff, s2, o);
    }
    float m = s * (1.0f / NC);
    float rs = rsqrtf(s2 * (1.0f / NC) - m * m + 1e-5f);
    float4 g0 = *(const float4*)(gam + lane * 4);
    float4 g1 = *(const float4*)(gam + 128 + lane * 4);
    float4 b0 = *(const float4*)(bet + lane * 4);
    float4 b1 = *(const float4*)(bet + 128 + lane * 4);
    bf16* dst = T + (size_t)t * NC;
    float o0x = (v0.x - m) * rs * g0.x + b0.x, o0y = (v0.y - m) * rs * g0.y + b0.y;
    float o0z = (v0.z - m) * rs * g0.z + b0.z, o0w = (v0.w - m) * rs * g0.w + b0.w;
    float o1x = (v1.x - m) * rs * g1.x + b1.x, o1y = (v1.y - m) * rs * g1.y + b1.y;
    float o1z = (v1.z - m) * rs * g1.z + b1.z, o1w = (v1.w - m) * rs * g1.w + b1.w;
    *(uint2*)(dst + lane * 4)       = make_uint2(f2bf2(o0x, o0y), f2bf2(o0z, o0w));
    *(uint2*)(dst + 128 + lane * 4) = make_uint2(f2bf2(o1x, o1y), f2bf2(o1z, o1w));
}

// ---------------- fused residual-add (permuted) + LN + permute-out ----------------
// r = base[t] + P[tp(addmode)]; Rout[t] = r; T[tout(lnmode)] = LN(r)
// addmode 0: window inverse; 1: grid scrambled-reverse inverse.
// lnmode 1: grid forward-gather inverse; 2: flat.
__global__ void resadd_ln(const float* __restrict__ base, const float* __restrict__ P,
                          float* __restrict__ Rout, const float* __restrict__ gam,
                          const float* __restrict__ bet, bf16* __restrict__ T,
                          int addmode, int lnmode) {
    int warp = threadIdx.x >> 5, lane = threadIdx.x & 31;
    int t = blockIdx.x * 8 + warp;
    int b = t >> 14, p = t & 16383;
    int h = p >> 7, w = p & 127;
    int tp;
    if (addmode == 0) {
        int win = (h >> 3) * 16 + (w >> 3);
        int pos = (h & 7) * 8 + (w & 7);
        tp = (b << 14) + win * 64 + pos;
    } else {
        int K2 = h >> 3, K1 = ((h & 7) << 1) | (w >> 6);
        int S1 = (w >> 3) & 7, S2 = w & 7;
        tp = (b << 14) + (K1 * 16 + K2) * 64 + S1 * 8 + S2;
    }
    const float* pb = base + (size_t)t * NC;
    const float* pp = P + (size_t)tp * NC;
    float4 v0 = *(const float4*)(pb + lane * 4);
    float4 v1 = *(const float4*)(pb + 128 + lane * 4);
    float4 q0 = *(const float4*)(pp + lane * 4);
    float4 q1 = *(const float4*)(pp + 128 + lane * 4);
    v0.x += q0.x; v0.y += q0.y; v0.z += q0.z; v0.w += q0.w;
    v1.x += q1.x; v1.y += q1.y; v1.z += q1.z; v1.w += q1.w;
    float* po = Rout + (size_t)t * NC;
    *(float4*)(po + lane * 4) = v0;
    *(float4*)(po + 128 + lane * 4) = v1;

    float s  = v0.x + v0.y + v0.z + v0.w + v1.x + v1.y + v1.z + v1.w;
    float s2 = v0.x * v0.x + v0.y * v0.y + v0.z * v0.z + v0.w * v0.w
             + v1.x * v1.x + v1.y * v1.y + v1.z * v1.z + v1.w * v1.w;
    #pragma unroll
    for (int o = 16; o; o >>= 1) {
        s  += __shfl_xor_sync(0xffffffff, s, o);
        s2 += __shfl_xor_sync(0xffffffff, s2, o);
    }
    float m = s * (1.0f / NC);
    float rs = rsqrtf(s2 * (1.0f / NC) - m * m + 1e-5f);
    float4 g0 = *(const float4*)(gam + lane * 4);
    float4 g1 = *(const float4*)(gam + 128 + lane * 4);
    float4 b0 = *(const float4*)(bet + lane * 4);
    float4 b1 = *(const float4*)(bet + 128 + lane * 4);
    int tout;
    if (lnmode == 2) tout = t;
    else {
        // grid forward gather inverse: token (wy=h&15, wx=w&15; py=h>>4, px=w>>4)
        tout = (b << 14) + ((h & 15) * 16 + (w & 15)) * 64 + (h >> 4) * 8 + (w >> 4);
    }
    bf16* dst = T + (size_t)tout * NC;
    float o0x = (v0.x - m) * rs * g0.x + b0.x, o0y = (v0.y - m) * rs * g0.y + b0.y;
    float o0z = (v0.z - m) * rs * g0.z + b0.z, o0w = (v0.w - m) * rs * g0.w + b0.w;
    float o1x = (v1.x - m) * rs * g1.x + b1.x, o1y = (v1.y - m) * rs * g1.y + b1.y;
    float o1z = (v1.z - m) * rs * g1.z + b1.z, o1w = (v1.w - m) * rs * g1.w + b1.w;
    *(uint2*)(dst + lane * 4)       = make_uint2(f2bf2(o0x, o0y), f2bf2(o0z, o0w));
    *(uint2*)(dst + 128 + lane * 4) = make_uint2(f2bf2(o1x, o1y), f2bf2(o1z, o1w));
}

// ================= bf16 NT GEMM: cp.async 3-stage + ldmatrix =================
// C[M,N] = A[M,K] * B[N,K]^T + bias[n]; 128x128 block, BK=64, 8 warps (2x4),
// warp tile 64x32. SMEM stage = A(16KB)+B(16KB); rows of 128B, 16B-group g of
// row r stored at (g ^ (r&7)) — conflict-free for cp.async stores and ldmatrix.
#define GSTAGE 32768
template<typename OutT, bool GELU>
__global__ __launch_bounds__(256, 1) void gemm_bf16_nt(
        const bf16* __restrict__ A, const bf16* __restrict__ B,
        const float* __restrict__ bias, OutT* __restrict__ C, int N, int K) {
    extern __shared__ uint8_t smem[];
    const uint32_t sbase = smem_u32(smem);
    const int tid = threadIdx.x;
    const int lane = tid & 31, warp = tid >> 5;
    const int wm = warp >> 2, wn = warp & 3;
    const int g = lane >> 2, q = lane & 3;
    const size_t m0 = (size_t)blockIdx.y * 128;
    const int n0 = blockIdx.x * 128;
    const bf16* Ag = A + m0 * K;
    const bf16* Bg = B + (size_t)n0 * K;
    const int ntiles = K >> 6;

    float acc[4][4][4];
    #pragma unroll
    for (int i = 0; i < 4; i++)
        #pragma unroll
        for (int j = 0; j < 4; j++)
            #pragma unroll
            for (int k = 0; k < 4; k++) acc[i][j][k] = 0.0f;

    // loader: 1024 16B chunks each for A and B per stage; id -> (row=id>>3, grp=id&7)
    auto load_stage = [&](int st, int k0) {
        uint32_t sa = sbase + st * GSTAGE;
        uint32_t sb = sa + 16384;
        #pragma unroll
        for (int i = 0; i < 4; i++) {
            int id = i * 256 + tid;
            int row = id >> 3, grp = id & 7;
            uint32_t soff = row * 128 + ((grp ^ (row & 7)) << 4);
            const bf16* ga = Ag + (size_t)row * K + k0 + grp * 8;
            const bf16* gb = Bg + (size_t)row * K + k0 + grp * 8;
            cp_async16(sa + soff, ga);
            cp_async16(sb + soff, gb);
        }
    };

    load_stage(0, 0);  cp_commit();
    load_stage(1, 64); cp_commit();
    cp_wait<1>();
    __syncthreads();

    for (int kt = 0; kt < ntiles; kt++) {
        if (kt + 2 < ntiles) load_stage((kt + 2) % 3, (kt + 2) << 6);
        cp_commit();   // empty group when nothing issued — keeps accounting uniform

        uint32_t sa = sbase + (kt % 3) * GSTAGE;
        uint32_t sb = sa + 16384;
        #pragma unroll
        for (int kc = 0; kc < 4; kc++) {
            uint32_t afr[4][4], bfr[4][2];
            int rsel = lane & 15;
            int gsel = kc * 2 + (lane >> 4);
            #pragma unroll
            for (int mt = 0; mt < 4; mt++) {
                int row = wm * 64 + mt * 16 + rsel;
                uint32_t addr = sa + row * 128 + ((gsel ^ (row & 7)) << 4);
                ldsm_x4(afr[mt][0], afr[mt][1], afr[mt][2], afr[mt][3], addr);
            }
            #pragma unroll
            for (int h = 0; h < 2; h++) {
                int row = wn * 32 + h * 16 + rsel;
                uint32_t addr = sb + row * 128 + ((gsel ^ (row & 7)) << 4);
                uint32_t x, y, z, w;
                ldsm_x4(x, y, z, w, addr);
                bfr[2 * h][0] = x;     bfr[2 * h][1] = z;
                bfr[2 * h + 1][0] = y; bfr[2 * h + 1][1] = w;
            }
            #pragma unroll
            for (int mt = 0; mt < 4; mt++)
                #pragma unroll
                for (int nt = 0; nt < 4; nt++)
                    mma_bf16(acc[mt][nt], afr[mt], bfr[nt]);
        }
        cp_wait<1>();
        __syncthreads();
    }

    #pragma unroll
    for (int mt = 0; mt < 4; mt++) {
        size_t rg = m0 + wm * 64 + mt * 16 + g;
        #pragma unroll
        for (int nt = 0; nt < 4; nt++) {
            int cb = n0 + wn * 32 + nt * 8 + 2 * q;
            float b0 = bias[cb], b1 = bias[cb + 1];
            float v0 = acc[mt][nt][0] + b0, v1 = acc[mt][nt][1] + b1;
            float v2 = acc[mt][nt][2] + b0, v3 = acc[mt][nt][3] + b1;
            if (GELU) {
                v0 = gelu_exact(v0); v1 = gelu_exact(v1);
                v2 = gelu_exact(v2); v3 = gelu_exact(v3);
            }
            if constexpr (sizeof(OutT) == 4) {
                *(float2*)&((float*)C)[rg * N + cb] = make_float2(v0, v1);
                *(float2*)&((float*)C)[(rg + 8) * N + cb] = make_float2(v2, v3);
            } else {
                *(uint32_t*)&((bf16*)C)[rg * N + cb] = f2bf2(v0, v1);
                *(uint32_t*)&((bf16*)C)[(rg + 8) * N + cb] = f2bf2(v2, v3);
            }
        }
    }
}

// ================= tensor-core attention, L=64, D=32 =================
__global__ void attn_kernel(const bf16* __restrict__ QKV, bf16* __restrict__ O) {
    __shared__ uint32_t sq[64 * 24];
    __shared__ uint32_t sk[64 * 24];
    __shared__ uint32_t sv[32 * 40];
    int wh = blockIdx.x;
    int win = wh >> 3, head = wh & 7;
    int tid = threadIdx.x;
    int warp = tid >> 5, lane = tid & 31;
    int g = lane >> 2, q = lane & 3;
    const bf16* base = QKV + (size_t)win * 64 * 768 + head * 32;

    {
        int r = tid >> 1, ch = tid & 1;
        int sw = ch ^ ((r >> 2) & 1);
        const bf16* src = base + (size_t)r * 768 + ch * 16;
        uint4 lo = *(const uint4*)src;
        uint4 hi = *(const uint4*)(src + 8);
        uint2* dst = (uint2*)(sq + r * 24 + sw * 8);
        dst[0] = make_uint2(lo.x, hi.x); dst[1] = make_uint2(lo.y, hi.y);
        dst[2] = make_uint2(lo.z, hi.z); dst[3] = make_uint2(lo.w, hi.w);
        lo = *(const uint4*)(src + 256);
        hi = *(const uint4*)(src + 264);
        dst = (uint2*)(sk + r * 24 + sw * 8);
        dst[0] = make_uint2(lo.x, hi.x); dst[1] = make_uint2(lo.y, hi.y);
        dst[2] = make_uint2(lo.z, hi.z); dst[3] = make_uint2(lo.w, hi.w);
    }
    {
        int jp = tid >> 2, d0 = (tid & 3) * 8;
        int j = jp * 2;
        const bf16* v0p = base + (size_t)j * 768 + 512 + d0;
        uint4 v0 = *(const uint4*)v0p;
        uint4 v1 = *(const uint4*)(v0p + 768);
        uint32_t u0[4] = {v0.x, v0.y, v0.z, v0.w};
        uint32_t u1[4] = {v1.x, v1.y, v1.z, v1.w};
        int cj = jp >> 3;
        int pr = jp & 7;
        int wp = ((pr & 3) << 1) | (pr >> 2);
        #pragma unroll
        for (int m = 0; m < 4; m++) {
            int d = d0 + 2 * m;
            uint32_t loP = (u0[m] & 0xffffu) | (u1[m] << 16);
            uint32_t hiP = (u0[m] >> 16) | (u1[m] & 0xffff0000u);
            sv[d * 40 + ((cj ^ ((d >> 2) & 3)) * 8) + wp] = loP;
            sv[(d + 1) * 40 + ((cj ^ (((d + 1) >> 2) & 3)) * 8) + wp] = hiP;
        }
    }
    __syncthreads();

    float sacc[8][4];
    #pragma unroll
    for (int nt = 0; nt < 8; nt++)
        #pragma unroll
        for (int i = 0; i < 4; i++) sacc[nt][i] = 0.0f;
    #pragma unroll
    for (int kc = 0; kc < 2; kc++) {
        int r0 = warp * 16 + g, r1 = r0 + 8;
        uint2 lo = *(uint2*)&sq[r0 * 24 + ((kc ^ ((r0 >> 2) & 1)) * 8) + 2 * q];
        uint2 hi = *(uint2*)&sq[r1 * 24 + ((kc ^ ((r1 >> 2) & 1)) * 8) + 2 * q];
        uint32_t a[4] = {lo.x, hi.x, lo.y, hi.y};
        #pragma unroll
        for (int nt = 0; nt < 8; nt++) {
            int rn = nt * 8 + g;
            uint2 bb = *(uint2*)&sk[rn * 24 + ((kc ^ ((rn >> 2) & 1)) * 8) + 2 * q];
            uint32_t bfv[2] = {bb.x, bb.y};
            mma_bf16(sacc[nt], a, bfv);
        }
    }

    const float scale = 0.17677669529663687f;
    #pragma unroll
    for (int nt = 0; nt < 8; nt++)
        #pragma unroll
        for (int i = 0; i < 4; i++) sacc[nt][i] *= scale;
    float mx0 = -1e30f, mx1 = -1e30f;
    #pragma unroll
    for (int nt = 0; nt < 8; nt++) {
        mx0 = fmaxf(mx0, fmaxf(sacc[nt][0], sacc[nt][1]));
        mx1 = fmaxf(mx1, fmaxf(sacc[nt][2], sacc[nt][3]));
    }
    mx0 = fmaxf(mx0, __shfl_xor_sync(0xffffffff, mx0, 1));
    mx0 = fmaxf(mx0, __shfl_xor_sync(0xffffffff, mx0, 2));
    mx1 = fmaxf(mx1, __shfl_xor_sync(0xffffffff, mx1, 1));
    mx1 = fmaxf(mx1, __shfl_xor_sync(0xffffffff, mx1, 2));
    float sum0 = 0.0f, sum1 = 0.0f;
    #pragma unroll
    for (int nt = 0; nt < 8; nt++) {
        sacc[nt][0] = __expf(sacc[nt][0] - mx0);
        sacc[nt][1] = __expf(sacc[nt][1] - mx0);
        sacc[nt][2] = __expf(sacc[nt][2] - mx1);
        sacc[nt][3] = __expf(sacc[nt][3] - mx1);
        sum0 += sacc[nt][0] + sacc[nt][1];
        sum1 += sacc[nt][2] + sacc[nt][3];
    }
    sum0 += __shfl_xor_sync(0xffffffff, sum0, 1);
    sum0 += __shfl_xor_sync(0xffffffff, sum0, 2);
    sum1 += __shfl_xor_sync(0xffffffff, sum1, 1);
    sum1 += __shfl_xor_sync(0xffffffff, sum1, 2);
    float inv0 = 1.0f / sum0, inv1 = 1.0f / sum1;
    #pragma unroll
    for (int nt = 0; nt < 8; nt++) {
        sacc[nt][0] *= inv0; sacc[nt][1] *= inv0;
        sacc[nt][2] *= inv1; sacc[nt][3] *= inv1;
    }

    float oacc[4][4];
    #pragma unroll
    for (int nt = 0; nt < 4; nt++)
        #pragma unroll
        for (int i = 0; i < 4; i++) oacc[nt][i] = 0.0f;
    #pragma unroll
    for (int kc = 0; kc < 4; kc++) {
        uint32_t a[4];
        a[0] = f2bf2(sacc[2 * kc][0], sacc[2 * kc][1]);
        a[1] = f2bf2(sacc[2 * kc][2], sacc[2 * kc][3]);
        a[2] = f2bf2(sacc[2 * kc + 1][0], sacc[2 * kc + 1][1]);
        a[3] = f2bf2(sacc[2 * kc + 1][2], sacc[2 * kc + 1][3]);
        #pragma unroll
        for (int nt = 0; nt < 4; nt++) {
            int rn = nt * 8 + g;
            uint2 bb = *(uint2*)&sv[rn * 40 + ((kc ^ ((rn >> 2) & 3)) * 8) + 2 * q];
            uint32_t bfv[2] = {bb.x, bb.y};
            mma_bf16(oacc[nt], a, bfv);
        }
    }

    int row0 = win * 64 + warp * 16 + g;
    bf16* o0 = O + (size_t)row0 * NC + head * 32;
    bf16* o1 = o0 + 8 * NC;
    #pragma unroll
    for (int nt = 0; nt < 4; nt++) {
        int cb = nt * 8 + 2 * q;
        *(uint32_t*)&o0[cb] = f2bf2(oacc[nt][0], oacc[nt][1]);
        *(uint32_t*)&o1[cb] = f2bf2(oacc[nt][2], oacc[nt][3]);
    }
}

// ---------------- launch ----------------
#define GEMM_SMEM 98304
extern "C" void kernel_launch(void* const* d_in, const int* in_sizes, int n_in,
                              void* d_out, int out_size) {
    const float* x      = (const float*)d_in[0];
    const float* w1     = (const float*)d_in[1];
    const float* b1     = (const float*)d_in[2];
    const float* w2     = (const float*)d_in[3];
    const float* b2     = (const float*)d_in[4];
    const float* w3     = (const float*)d_in[5];
    const float* b3     = (const float*)d_in[6];
    const float* wf     = (const float*)d_in[7];
    const float* bf     = (const float*)d_in[8];
    const float* gw     = (const float*)d_in[9];
    const float* bw     = (const float*)d_in[10];
    const float* wqkv_w = (const float*)d_in[11];
    const float* bqkv_w = (const float*)d_in[12];
    const float* wo_w   = (const float*)d_in[13];
    const float* bo_w   = (const float*)d_in[14];
    const float* gg     = (const float*)d_in[15];
    const float* bg     = (const float*)d_in[16];
    const float* wqkv_g = (const float*)d_in[17];
    const float* bqkv_g = (const float*)d_in[18];
    const float* wo_g   = (const float*)d_in[19];
    const float* bo_g   = (const float*)d_in[20];
    const float* gm     = (const float*)d_in[21];
    const float* bm     = (const float*)d_in[22];
    const float* m1w    = (const float*)d_in[23];
    const float* m1b    = (const float*)d_in[24];
    const float* m2w    = (const float*)d_in[25];
    const float* m2b    = (const float*)d_in[26];
    float* out = (float*)d_out;

    static bool attrs_set = false;
    if (!attrs_set) {
        cudaFuncSetAttribute(gemm_bf16_nt<float, false>,
                             cudaFuncAttributeMaxDynamicSharedMemorySize, GEMM_SMEM);
        cudaFuncSetAttribute(gemm_bf16_nt<bf16, false>,
                             cudaFuncAttributeMaxDynamicSharedMemorySize, GEMM_SMEM);
        cudaFuncSetAttribute(gemm_bf16_nt<bf16, true>,
                             cudaFuncAttributeMaxDynamicSharedMemorySize, GEMM_SMEM);
        attrs_set = true;
    }

    void *p_cat, *p_catt, *p_xm, *p_xtok, *p_tok, *p_qkv, *p_att, *p_proj, *p_h1, *p_wb;
    cudaGetSymbolAddress(&p_cat, g_cat);
    cudaGetSymbolAddress(&p_catt, g_catt);
    cudaGetSymbolAddress(&p_xm, g_xm);
    cudaGetSymbolAddress(&p_xtok, g_xtok);
    cudaGetSymbolAddress(&p_tok, g_tok);
    cudaGetSymbolAddress(&p_qkv, g_qkv);
    cudaGetSymbolAddress(&p_att, g_att);
    cudaGetSymbolAddress(&p_proj, g_proj);
    cudaGetSymbolAddress(&p_h1, g_h1);
    cudaGetSymbolAddress(&p_wb, g_wb);
    bf16* cat  = (bf16*)p_cat;    bf16* catt = (bf16*)p_catt;
    float* xm  = (float*)p_xm;    float* xtok = (float*)p_xtok;
    bf16* tok  = (bf16*)p_tok;    bf16* qkv  = (bf16*)p_qkv;
    bf16* att  = (bf16*)p_att;    float* proj = (float*)p_proj;
    bf16* h1   = (bf16*)p_h1;     bf16* wb   = (bf16*)p_wb;

    // all weight conversions in one launch
    cvt_all<<<1216, 256>>>(wf, wqkv_w, wqkv_g, wo_w, wo_g, m1w, m2w, wb);

    // depthwise convs -> cat (bf16); transpose to token-major; x -> token-major
    dwconv3_kernel<<<dim3(16, NC, NB), 256>>>(x, w1, b1, w2, b2, w3, b3);
    cat_transpose<<<dim3(256, 12, NB), 256>>>(cat, catt);
    to_tok<<<dim3(256, 4, NB), 256>>>(x, xtok);

    // 1x1 fuse as NT GEMM -> xm (fp32, token-major)
    gemm_bf16_nt<float, false><<<dim3(2, 1024), 256, GEMM_SMEM>>>(catt, wb + OFF_WF, bf, xm, 256, 768);

    // ---- window branch ----
    ln_perm<<<16384, 256>>>(xm, gw, bw, tok, 0);
    gemm_bf16_nt<bf16, false><<<dim3(6, 1024), 256, GEMM_SMEM>>>(tok, wb + OFF_QKVW, bqkv_w, qkv, 768, 256);
    attn_kernel<<<16384, 128>>>(qkv, att);
    gemm_bf16_nt<float, false><<<dim3(2, 1024), 256, GEMM_SMEM>>>(att, wb + OFF_WOW, bo_w, proj, 256, 256);
    // fused: xm = xtok + perm(proj); tok = LN_grid(xm)
    resadd_ln<<<16384, 256>>>(xtok, proj, xm, gg, bg, tok, 0, 1);

    // ---- grid branch ----
    gemm_bf16_nt<bf16, false><<<dim3(6, 1024), 256, GEMM_SMEM>>>(tok, wb + OFF_QKVG, bqkv_g, qkv, 768, 256);
    attn_kernel<<<16384, 128>>>(qkv, att);
    gemm_bf16_nt<float, false><<<dim3(2, 1024), 256, GEMM_SMEM>>>(att, wb + OFF_WOG, bo_g, proj, 256, 256);
    // fused: xm = xm + perm(proj); tok = LN_flat(xm)
    resadd_ln<<<16384, 256>>>(xm, proj, xm, gm, bm, tok, 1, 2);

    // ---- MLP ----
    gemm_bf16_nt<bf16, true ><<<dim3(8, 1024), 256, GEMM_SMEM>>>(tok, wb + OFF_M1, m1b, h1, 1024, 256);
    gemm_bf16_nt<float, false><<<dim3(2, 1024), 256, GEMM_SMEM>>>(h1, wb + OFF_M2, m2b, proj, 256, 1024);
    from_tok_add<<<dim3(256, 4, NB), 256>>>(xm, proj, out);
}